// round 1
// baseline (speedup 1.0000x reference)
#include <cuda_runtime.h>
#include <cuda_bf16.h>
#include <cstddef>

#define NN 50000
#define EE 800000
#define DD 128
#define RR 8
#define BB 4
#define LL 2
#define KOUT 1152              // (R+1)*D : 8 relations + self loop
#define BN_EPS 1e-3f

// ---------------- device scratch (no allocations allowed) ----------------
__device__ float g_h[(size_t)NN * DD];          // 25.6 MB
__device__ float g_T[(size_t)NN * KOUT];        // 230.4 MB
__device__ float g_agg[(size_t)NN * DD];        // 25.6 MB
__device__ float g_Wcat[(size_t)DD * KOUT];     // 0.59 MB
__device__ int   g_cnt[(size_t)RR * NN];        // 1.6 MB
__device__ float g_nodenorm[NN];                // 0.2 MB

// ---------------- edge-type counts ----------------
__global__ __launch_bounds__(256) void count_kernel(const int* __restrict__ dst,
                                                    const int* __restrict__ etype,
                                                    int* __restrict__ cnt) {
    int e = blockIdx.x * blockDim.x + threadIdx.x;
    if (e >= EE) return;
    atomicAdd(&cnt[(size_t)etype[e] * NN + dst[e]], 1);
}

// node_norm[n] = 1/cnt[r*] for largest r with cnt>0 (later types overwrite earlier)
__global__ __launch_bounds__(256) void norm_kernel(const int* __restrict__ cnt,
                                                   float* __restrict__ nodenorm) {
    int n = blockIdx.x * blockDim.x + threadIdx.x;
    if (n >= NN) return;
    float v = 0.f;
    #pragma unroll
    for (int r = RR - 1; r >= 0; --r) {
        int c = cnt[(size_t)r * NN + n];
        if (c > 0) { v = 1.0f / (float)c; break; }
    }
    nodenorm[n] = v;
}

// ---------------- basis combination: Wcat [D, 1152] row-major ----------------
// Wcat[d, r*128+f] = sum_b w_coe[l,r,b]*bases[l,b,d,f]   (r<8)
// Wcat[d, 8*128+f] = self_loop[l,d,f]
__global__ __launch_bounds__(256) void basis_kernel(const float* __restrict__ bases,
                                                    const float* __restrict__ w_coe,
                                                    const float* __restrict__ self_loop,
                                                    float* __restrict__ Wcat, int l) {
    int idx = blockIdx.x * blockDim.x + threadIdx.x;
    if (idx >= DD * KOUT) return;
    int d = idx / KOUT;
    int c = idx - d * KOUT;
    int r = c >> 7;
    int f = c & 127;
    float v;
    if (r < RR) {
        v = 0.f;
        #pragma unroll
        for (int b = 0; b < BB; ++b)
            v += w_coe[(size_t)l * RR * BB + r * BB + b] *
                 bases[(size_t)l * BB * DD * DD + (size_t)b * DD * DD + (size_t)d * DD + f];
    } else {
        v = self_loop[(size_t)l * DD * DD + (size_t)d * DD + f];
    }
    Wcat[idx] = v;
}

// ---------------- fp32 tiled GEMM: C[M,Ncol] = A[M,K] @ B[K,Ncol] (+bias) ----------------
// 64x64 block, 256 threads, 4x4 microtile, K tiled by 64.
__global__ __launch_bounds__(256) void gemm64(const float* __restrict__ A,
                                              const float* __restrict__ B,
                                              const float* __restrict__ bias,
                                              float* __restrict__ C,
                                              int M, int K, int Ncol) {
    __shared__ float As[64][68];   // transposed: As[k][m], padded for alignment
    __shared__ float Bs[64][64];   // Bs[k][n]
    const int tid = threadIdx.x;
    const int tm  = tid >> 4;      // 0..15
    const int tn  = tid & 15;      // 0..15
    const int row0 = blockIdx.y * 64;
    const int col0 = blockIdx.x * 64;

    float acc[4][4];
    #pragma unroll
    for (int i = 0; i < 4; ++i)
        #pragma unroll
        for (int j = 0; j < 4; ++j) acc[i][j] = 0.f;

    for (int kt = 0; kt < K; kt += 64) {
        // Load A tile (64 rows x 64 k), transposed into As[k][m]
        #pragma unroll
        for (int i = 0; i < 4; ++i) {
            int m  = (tid >> 4) + i * 16;
            int k4 = (tid & 15);
            int gr = row0 + m;
            float4 v = make_float4(0.f, 0.f, 0.f, 0.f);
            if (gr < M) v = *(const float4*)(A + (size_t)gr * K + kt + k4 * 4);
            As[k4 * 4 + 0][m] = v.x;
            As[k4 * 4 + 1][m] = v.y;
            As[k4 * 4 + 2][m] = v.z;
            As[k4 * 4 + 3][m] = v.w;
        }
        // Load B tile (64 k x 64 cols)
        #pragma unroll
        for (int i = 0; i < 4; ++i) {
            int k  = (tid >> 4) + i * 16;
            int n4 = (tid & 15);
            float4 v = *(const float4*)(B + (size_t)(kt + k) * Ncol + col0 + n4 * 4);
            *(float4*)&Bs[k][n4 * 4] = v;
        }
        __syncthreads();
        #pragma unroll
        for (int k = 0; k < 64; ++k) {
            float4 a = *(const float4*)&As[k][tm * 4];
            float4 b = *(const float4*)&Bs[k][tn * 4];
            acc[0][0] += a.x * b.x; acc[0][1] += a.x * b.y; acc[0][2] += a.x * b.z; acc[0][3] += a.x * b.w;
            acc[1][0] += a.y * b.x; acc[1][1] += a.y * b.y; acc[1][2] += a.y * b.z; acc[1][3] += a.y * b.w;
            acc[2][0] += a.z * b.x; acc[2][1] += a.z * b.y; acc[2][2] += a.z * b.z; acc[2][3] += a.z * b.w;
            acc[3][0] += a.w * b.x; acc[3][1] += a.w * b.y; acc[3][2] += a.w * b.z; acc[3][3] += a.w * b.w;
        }
        __syncthreads();
    }

    float4 bv = make_float4(0.f, 0.f, 0.f, 0.f);
    if (bias) bv = *(const float4*)(bias + col0 + tn * 4);
    #pragma unroll
    for (int i = 0; i < 4; ++i) {
        int gr = row0 + tm * 4 + i;
        if (gr < M) {
            float4 o = make_float4(acc[i][0] + bv.x, acc[i][1] + bv.y,
                                   acc[i][2] + bv.z, acc[i][3] + bv.w);
            *(float4*)(C + (size_t)gr * Ncol + col0 + tn * 4) = o;
        }
    }
}

// ---------------- agg init from self-loop slice of T ----------------
__global__ __launch_bounds__(256) void agginit_kernel(const float* __restrict__ T,
                                                      float* __restrict__ agg) {
    int idx = blockIdx.x * blockDim.x + threadIdx.x;   // over N*32 float4s
    if (idx >= NN * 32) return;
    int n = idx >> 5;
    int q = idx & 31;
    const float4* tp = (const float4*)(T + (size_t)n * KOUT + RR * DD);
    ((float4*)agg)[(size_t)n * 32 + q] = tp[q];
}

// ---------------- edge scatter: one warp per edge ----------------
__global__ __launch_bounds__(256) void scatter_kernel(const float* __restrict__ T,
                                                      const int* __restrict__ src,
                                                      const int* __restrict__ dst,
                                                      const int* __restrict__ etype,
                                                      const float* __restrict__ nodenorm,
                                                      float* __restrict__ agg) {
    int warp = (blockIdx.x * blockDim.x + threadIdx.x) >> 5;
    int lane = threadIdx.x & 31;
    if (warp >= EE) return;
    int s = src[warp];
    int t = dst[warp];
    int r = etype[warp];
    float nrm = nodenorm[t];
    const float4* tp = (const float4*)(T + (size_t)s * KOUT + (size_t)r * DD);
    float4 v = tp[lane];
    float* out = agg + (size_t)t * DD + lane * 4;
    asm volatile("red.global.add.v4.f32 [%0], {%1, %2, %3, %4};"
                 :: "l"(out), "f"(v.x * nrm), "f"(v.y * nrm), "f"(v.z * nrm), "f"(v.w * nrm)
                 : "memory");
}

// ---------------- BN (inference) + ReLU ----------------
__global__ __launch_bounds__(256) void bnrelu_kernel(const float* __restrict__ agg,
                                                     const float* __restrict__ gamma,
                                                     const float* __restrict__ beta,
                                                     const float* __restrict__ mean,
                                                     const float* __restrict__ var,
                                                     float* __restrict__ h) {
    int idx = blockIdx.x * blockDim.x + threadIdx.x;
    if (idx >= NN * DD) return;
    int f = idx & 127;
    float x = agg[idx];
    float y = gamma[f] * (x - mean[f]) * rsqrtf(var[f] + BN_EPS) + beta[f];
    h[idx] = fmaxf(y, 0.f);
}

// ---------------- launcher ----------------
extern "C" void kernel_launch(void* const* d_in, const int* in_sizes, int n_in,
                              void* d_out, int out_size) {
    const float* node_feat = (const float*)d_in[0];
    const float* W_emb     = (const float*)d_in[1];
    const float* b_emb     = (const float*)d_in[2];
    const float* bases     = (const float*)d_in[3];
    const float* w_coe     = (const float*)d_in[4];
    const float* self_loop = (const float*)d_in[5];
    const float* bn_gamma  = (const float*)d_in[6];
    const float* bn_beta   = (const float*)d_in[7];
    const float* bn_mean   = (const float*)d_in[8];
    const float* bn_var    = (const float*)d_in[9];
    const int*   src       = (const int*)d_in[10];
    const int*   dst       = (const int*)d_in[11];
    const int*   etype     = (const int*)d_in[12];

    float *h, *T, *agg, *Wcat, *nodenorm;
    int *cnt;
    cudaGetSymbolAddress((void**)&h, g_h);
    cudaGetSymbolAddress((void**)&T, g_T);
    cudaGetSymbolAddress((void**)&agg, g_agg);
    cudaGetSymbolAddress((void**)&Wcat, g_Wcat);
    cudaGetSymbolAddress((void**)&cnt, g_cnt);
    cudaGetSymbolAddress((void**)&nodenorm, g_nodenorm);

    // edge norms
    cudaMemsetAsync(cnt, 0, (size_t)RR * NN * sizeof(int));
    count_kernel<<<(EE + 255) / 256, 256>>>(dst, etype, cnt);
    norm_kernel<<<(NN + 255) / 256, 256>>>(cnt, nodenorm);

    // embedding: h = node_feat @ W_emb + b_emb
    {
        dim3 grid(DD / 64, (NN + 63) / 64);
        gemm64<<<grid, 256>>>(node_feat, W_emb, b_emb, h, NN, DD, DD);
    }

    for (int l = 0; l < LL; ++l) {
        basis_kernel<<<(DD * KOUT + 255) / 256, 256>>>(bases, w_coe, self_loop, Wcat, l);
        {
            dim3 grid(KOUT / 64, (NN + 63) / 64);
            gemm64<<<grid, 256>>>(h, Wcat, nullptr, T, NN, DD, KOUT);
        }
        agginit_kernel<<<(NN * 32 + 255) / 256, 256>>>(T, agg);
        scatter_kernel<<<(EE * 32 + 255) / 256, 256>>>(T, src, dst, etype, nodenorm, agg);
        bnrelu_kernel<<<(NN * DD + 255) / 256, 256>>>(agg,
                                                      bn_gamma + (size_t)l * DD,
                                                      bn_beta  + (size_t)l * DD,
                                                      bn_mean  + (size_t)l * DD,
                                                      bn_var   + (size_t)l * DD,
                                                      h);
    }

    cudaMemcpyAsync(d_out, h, (size_t)NN * DD * sizeof(float), cudaMemcpyDeviceToDevice);
}

// round 3
// speedup vs baseline: 1.6772x; 1.6772x over previous
#include <cuda_runtime.h>
#include <cuda_bf16.h>
#include <cstdint>
#include <cstddef>

#define NN 50000
#define EE 800000
#define DD 128
#define RR 8
#define BB 4
#define LL 2
#define KOUT 1152              // (R+1)*D : 8 relations + self loop
#define BN_EPS 1e-3f
#define ASTRIDE 136            // padded smem row stride (elements)

// ---------------- device scratch (no allocations allowed) ----------------
__device__ float          g_h[(size_t)NN * DD];
__device__ __nv_bfloat16  g_h_hi[(size_t)NN * DD];
__device__ __nv_bfloat16  g_h_lo[(size_t)NN * DD];
__device__ __nv_bfloat16  g_nf_hi[(size_t)NN * DD];
__device__ __nv_bfloat16  g_nf_lo[(size_t)NN * DD];
__device__ float          g_T[(size_t)NN * KOUT];
__device__ float          g_agg[(size_t)NN * DD];
__device__ __nv_bfloat16  g_WcatT_hi[(size_t)KOUT * DD];
__device__ __nv_bfloat16  g_WcatT_lo[(size_t)KOUT * DD];
__device__ __nv_bfloat16  g_WembT_hi[(size_t)DD * DD];
__device__ __nv_bfloat16  g_WembT_lo[(size_t)DD * DD];
__device__ int            g_cnt[(size_t)RR * NN];
__device__ float          g_nodenorm[NN];

// ================= helpers =================
__device__ __forceinline__ uint32_t smem_to_u32(const void* p) {
    uint32_t a;
    asm("{ .reg .u64 t; cvta.to.shared.u64 t, %1; cvt.u32.u64 %0, t; }" : "=r"(a) : "l"(p));
    return a;
}

__device__ __forceinline__ void ldm_x4(uint32_t* r, uint32_t addr) {
    asm volatile("ldmatrix.sync.aligned.m8n8.x4.shared.b16 {%0,%1,%2,%3}, [%4];"
                 : "=r"(r[0]), "=r"(r[1]), "=r"(r[2]), "=r"(r[3]) : "r"(addr));
}

__device__ __forceinline__ void mma16816(float* d, const uint32_t* a, const uint32_t* b) {
    asm volatile("mma.sync.aligned.m16n8k16.row.col.f32.bf16.bf16.f32 "
                 "{%0,%1,%2,%3}, {%4,%5,%6,%7}, {%8,%9}, {%0,%1,%2,%3};"
                 : "+f"(d[0]), "+f"(d[1]), "+f"(d[2]), "+f"(d[3])
                 : "r"(a[0]), "r"(a[1]), "r"(a[2]), "r"(a[3]), "r"(b[0]), "r"(b[1]));
}

// ================= tensor-core (HMMA) GEMM =================
// C[M, Ncol] = (Ahi+Alo)[M,128] @ ((Bhi+Blo)[Ncol,128])^T  (3-term split, fp32 accum)
// CTA tile 128x128; 8 warps (2 along M x 4 along N), warp tile 64x32.
#define SMEM_GEMM_TOTAL (4 * 128 * ASTRIDE * 2)

__global__ __launch_bounds__(256)
void mma_gemm(const __nv_bfloat16* __restrict__ Ahi, const __nv_bfloat16* __restrict__ Alo,
              const __nv_bfloat16* __restrict__ Bhi, const __nv_bfloat16* __restrict__ Blo,
              const float* __restrict__ bias, float* __restrict__ C, int M, int Ncol) {
    extern __shared__ __nv_bfloat16 smem[];
    __nv_bfloat16* sAhi = smem;
    __nv_bfloat16* sAlo = sAhi + 128 * ASTRIDE;
    __nv_bfloat16* sBhi = sAlo + 128 * ASTRIDE;
    __nv_bfloat16* sBlo = sBhi + 128 * ASTRIDE;

    const int tid = threadIdx.x;
    const int wid = tid >> 5;
    const int lane = tid & 31;
    const int warp_m = wid >> 2;          // 0..1  (64 rows each)
    const int warp_n = wid & 3;           // 0..3  (32 cols each)
    const int m0 = blockIdx.y * 128;
    const int c0 = blockIdx.x * 128;

    // ---- cooperative load: 4 tiles of [128 x 128] bf16, padded stride ----
    #pragma unroll 4
    for (int i = tid; i < 2048; i += 256) {
        int row = i >> 4, kc = i & 15;
        int gr = m0 + row;
        uint4 vh = make_uint4(0, 0, 0, 0), vl = make_uint4(0, 0, 0, 0);
        if (gr < M) {
            vh = *(const uint4*)(Ahi + (size_t)gr * 128 + kc * 8);
            vl = *(const uint4*)(Alo + (size_t)gr * 128 + kc * 8);
        }
        *(uint4*)(sAhi + row * ASTRIDE + kc * 8) = vh;
        *(uint4*)(sAlo + row * ASTRIDE + kc * 8) = vl;
    }
    #pragma unroll 4
    for (int i = tid; i < 2048; i += 256) {
        int row = i >> 4, kc = i & 15;
        int gr = c0 + row;     // Ncol is a multiple of 128
        uint4 vh = *(const uint4*)(Bhi + (size_t)gr * 128 + kc * 8);
        uint4 vl = *(const uint4*)(Blo + (size_t)gr * 128 + kc * 8);
        *(uint4*)(sBhi + row * ASTRIDE + kc * 8) = vh;
        *(uint4*)(sBlo + row * ASTRIDE + kc * 8) = vl;
    }
    __syncthreads();

    float acc[4][4][4];
    #pragma unroll
    for (int a = 0; a < 4; ++a)
        #pragma unroll
        for (int b = 0; b < 4; ++b)
            #pragma unroll
            for (int c = 0; c < 4; ++c) acc[a][b][c] = 0.f;

    const uint32_t uAhi = smem_to_u32(sAhi);
    const uint32_t uAlo = smem_to_u32(sAlo);
    const uint32_t uBhi = smem_to_u32(sBhi);
    const uint32_t uBlo = smem_to_u32(sBlo);

    // A ldmatrix lane pattern: row = base + (lane&15), col = (lane>>4)*8
    const int a_row_off = (warp_m * 64 + (lane & 15)) * ASTRIDE + ((lane >> 4) << 3);
    // B ldmatrix lane pattern: n = base + (lane&7) + ((lane>>4)&1)*8, col = ((lane>>3)&1)*8
    const int b_row_off = (warp_n * 32 + (lane & 7) + (((lane >> 4) & 1) << 3)) * ASTRIDE
                          + (((lane >> 3) & 1) << 3);

    const uint32_t baseA[3] = {uAhi, uAlo, uAhi};
    const uint32_t baseB[3] = {uBhi, uBhi, uBlo};

    #pragma unroll
    for (int p = 0; p < 3; ++p) {
        const uint32_t bA = baseA[p];
        const uint32_t bB = baseB[p];
        #pragma unroll
        for (int ks = 0; ks < 8; ++ks) {
            const int k0 = ks * 16;
            uint32_t afr[4][4];
            #pragma unroll
            for (int mt = 0; mt < 4; ++mt)
                ldm_x4(afr[mt], bA + (uint32_t)(a_row_off + mt * 16 * ASTRIDE + k0) * 2);
            uint32_t bfr[4][2];
            #pragma unroll
            for (int nt2 = 0; nt2 < 2; ++nt2) {
                uint32_t r[4];
                ldm_x4(r, bB + (uint32_t)(b_row_off + nt2 * 16 * ASTRIDE + k0) * 2);
                bfr[nt2 * 2 + 0][0] = r[0]; bfr[nt2 * 2 + 0][1] = r[1];
                bfr[nt2 * 2 + 1][0] = r[2]; bfr[nt2 * 2 + 1][1] = r[3];
            }
            #pragma unroll
            for (int mt = 0; mt < 4; ++mt)
                #pragma unroll
                for (int nt = 0; nt < 4; ++nt)
                    mma16816(acc[mt][nt], afr[mt], bfr[nt]);
        }
    }

    // ---- epilogue ----
    const int mrow = m0 + warp_m * 64 + (lane >> 2);
    const int ncol = c0 + warp_n * 32 + 2 * (lane & 3);
    #pragma unroll
    for (int mt = 0; mt < 4; ++mt) {
        #pragma unroll
        for (int half = 0; half < 2; ++half) {
            int gr = mrow + mt * 16 + half * 8;
            if (gr < M) {
                float* dst = C + (size_t)gr * Ncol + ncol;
                #pragma unroll
                for (int nt = 0; nt < 4; ++nt) {
                    float2 o;
                    o.x = acc[mt][nt][half * 2 + 0];
                    o.y = acc[mt][nt][half * 2 + 1];
                    if (bias) {
                        o.x += bias[ncol + nt * 8];
                        o.y += bias[ncol + nt * 8 + 1];
                    }
                    *(float2*)(dst + nt * 8) = o;
                }
            }
        }
    }
}

// ================= small kernels =================
__global__ __launch_bounds__(256) void count_kernel(const int* __restrict__ dst,
                                                    const int* __restrict__ etype,
                                                    int* __restrict__ cnt) {
    int e = blockIdx.x * blockDim.x + threadIdx.x;
    if (e >= EE) return;
    atomicAdd(&cnt[(size_t)etype[e] * NN + dst[e]], 1);
}

__global__ __launch_bounds__(256) void norm_kernel(const int* __restrict__ cnt,
                                                   float* __restrict__ nodenorm) {
    int n = blockIdx.x * blockDim.x + threadIdx.x;
    if (n >= NN) return;
    float v = 0.f;
    #pragma unroll
    for (int r = RR - 1; r >= 0; --r) {
        int c = cnt[(size_t)r * NN + n];
        if (c > 0) { v = 1.0f / (float)c; break; }
    }
    nodenorm[n] = v;
}

__global__ __launch_bounds__(256) void split_kernel(const float* __restrict__ x,
                                                    __nv_bfloat16* __restrict__ hi,
                                                    __nv_bfloat16* __restrict__ lo, int n) {
    int i = blockIdx.x * blockDim.x + threadIdx.x;
    if (i >= n) return;
    float v = x[i];
    __nv_bfloat16 h = __float2bfloat16(v);
    hi[i] = h;
    lo[i] = __float2bfloat16(v - __bfloat162float(h));
}

// WembT[n, k] = W_emb[k, n], split hi/lo
__global__ __launch_bounds__(256) void wemb_kernel(const float* __restrict__ W,
                                                   __nv_bfloat16* __restrict__ hi,
                                                   __nv_bfloat16* __restrict__ lo) {
    int i = blockIdx.x * blockDim.x + threadIdx.x;
    if (i >= DD * DD) return;
    int n = i >> 7, k = i & 127;
    float v = W[(size_t)k * DD + n];
    __nv_bfloat16 h = __float2bfloat16(v);
    hi[i] = h;
    lo[i] = __float2bfloat16(v - __bfloat162float(h));
}

// WcatT[c, d]: c=r*128+f; r<8 -> sum_b w_coe[l,r,b]*bases[l,b,d,f]; r==8 -> self_loop[l,d,f]
__global__ __launch_bounds__(256) void wcat_kernel(const float* __restrict__ bases,
                                                   const float* __restrict__ w_coe,
                                                   const float* __restrict__ self_loop,
                                                   __nv_bfloat16* __restrict__ hi,
                                                   __nv_bfloat16* __restrict__ lo, int l) {
    int i = blockIdx.x * blockDim.x + threadIdx.x;
    if (i >= KOUT * DD) return;
    int c = i >> 7, d = i & 127;
    int r = c >> 7, f = c & 127;
    float v;
    if (r < RR) {
        v = 0.f;
        #pragma unroll
        for (int b = 0; b < BB; ++b)
            v += w_coe[(size_t)l * RR * BB + r * BB + b] *
                 bases[(size_t)l * BB * DD * DD + (size_t)b * DD * DD + (size_t)d * DD + f];
    } else {
        v = self_loop[(size_t)l * DD * DD + (size_t)d * DD + f];
    }
    __nv_bfloat16 h = __float2bfloat16(v);
    hi[i] = h;
    lo[i] = __float2bfloat16(v - __bfloat162float(h));
}

__global__ __launch_bounds__(256) void agginit_kernel(const float* __restrict__ T,
                                                      float* __restrict__ agg) {
    int idx = blockIdx.x * blockDim.x + threadIdx.x;
    if (idx >= NN * 32) return;
    int n = idx >> 5;
    int q = idx & 31;
    const float4* tp = (const float4*)(T + (size_t)n * KOUT + RR * DD);
    ((float4*)agg)[(size_t)n * 32 + q] = tp[q];
}

__global__ __launch_bounds__(256) void scatter_kernel(const float* __restrict__ T,
                                                      const int* __restrict__ src,
                                                      const int* __restrict__ dst,
                                                      const int* __restrict__ etype,
                                                      const float* __restrict__ nodenorm,
                                                      float* __restrict__ agg) {
    int warp = (blockIdx.x * blockDim.x + threadIdx.x) >> 5;
    int lane = threadIdx.x & 31;
    if (warp >= EE) return;
    int s = src[warp];
    int t = dst[warp];
    int r = etype[warp];
    float nrm = nodenorm[t];
    const float4* tp = (const float4*)(T + (size_t)s * KOUT + (size_t)r * DD);
    float4 v = tp[lane];
    float* out = agg + (size_t)t * DD + lane * 4;
    asm volatile("red.global.add.v4.f32 [%0], {%1, %2, %3, %4};"
                 :: "l"(out), "f"(v.x * nrm), "f"(v.y * nrm), "f"(v.z * nrm), "f"(v.w * nrm)
                 : "memory");
}

// BN + ReLU + split for next layer's GEMM inputs
__global__ __launch_bounds__(256) void bnrelu_kernel(const float* __restrict__ agg,
                                                     const float* __restrict__ gamma,
                                                     const float* __restrict__ beta,
                                                     const float* __restrict__ mean,
                                                     const float* __restrict__ var,
                                                     float* __restrict__ h,
                                                     __nv_bfloat16* __restrict__ hhi,
                                                     __nv_bfloat16* __restrict__ hlo) {
    int idx = blockIdx.x * blockDim.x + threadIdx.x;
    if (idx >= NN * DD) return;
    int f = idx & 127;
    float x = agg[idx];
    float y = gamma[f] * (x - mean[f]) * rsqrtf(var[f] + BN_EPS) + beta[f];
    y = fmaxf(y, 0.f);
    h[idx] = y;
    __nv_bfloat16 yh = __float2bfloat16(y);
    hhi[idx] = yh;
    hlo[idx] = __float2bfloat16(y - __bfloat162float(yh));
}

// ================= launcher =================
extern "C" void kernel_launch(void* const* d_in, const int* in_sizes, int n_in,
                              void* d_out, int out_size) {
    const float* node_feat = (const float*)d_in[0];
    const float* W_emb     = (const float*)d_in[1];
    const float* b_emb     = (const float*)d_in[2];
    const float* bases     = (const float*)d_in[3];
    const float* w_coe     = (const float*)d_in[4];
    const float* self_loop = (const float*)d_in[5];
    const float* bn_gamma  = (const float*)d_in[6];
    const float* bn_beta   = (const float*)d_in[7];
    const float* bn_mean   = (const float*)d_in[8];
    const float* bn_var    = (const float*)d_in[9];
    const int*   src       = (const int*)d_in[10];
    const int*   dst       = (const int*)d_in[11];
    const int*   etype     = (const int*)d_in[12];

    float *h, *T, *agg, *nodenorm;
    __nv_bfloat16 *h_hi, *h_lo, *nf_hi, *nf_lo, *WcT_hi, *WcT_lo, *WeT_hi, *WeT_lo;
    int* cnt;
    cudaGetSymbolAddress((void**)&h, g_h);
    cudaGetSymbolAddress((void**)&T, g_T);
    cudaGetSymbolAddress((void**)&agg, g_agg);
    cudaGetSymbolAddress((void**)&nodenorm, g_nodenorm);
    cudaGetSymbolAddress((void**)&cnt, g_cnt);
    cudaGetSymbolAddress((void**)&h_hi, g_h_hi);
    cudaGetSymbolAddress((void**)&h_lo, g_h_lo);
    cudaGetSymbolAddress((void**)&nf_hi, g_nf_hi);
    cudaGetSymbolAddress((void**)&nf_lo, g_nf_lo);
    cudaGetSymbolAddress((void**)&WcT_hi, g_WcatT_hi);
    cudaGetSymbolAddress((void**)&WcT_lo, g_WcatT_lo);
    cudaGetSymbolAddress((void**)&WeT_hi, g_WembT_hi);
    cudaGetSymbolAddress((void**)&WeT_lo, g_WembT_lo);

    cudaFuncSetAttribute(mma_gemm, cudaFuncAttributeMaxDynamicSharedMemorySize, SMEM_GEMM_TOTAL);

    // edge norms
    cudaMemsetAsync(cnt, 0, (size_t)RR * NN * sizeof(int));
    count_kernel<<<(EE + 255) / 256, 256>>>(dst, etype, cnt);
    norm_kernel<<<(NN + 255) / 256, 256>>>(cnt, nodenorm);

    // weight + input prep
    wemb_kernel<<<(DD * DD + 255) / 256, 256>>>(W_emb, WeT_hi, WeT_lo);
    split_kernel<<<(NN * DD + 255) / 256, 256>>>(node_feat, nf_hi, nf_lo, NN * DD);

    // embedding: h = node_feat @ W_emb + b_emb   (HMMA)
    {
        dim3 grid(1, (NN + 127) / 128);
        mma_gemm<<<grid, 256, SMEM_GEMM_TOTAL>>>(nf_hi, nf_lo, WeT_hi, WeT_lo, b_emb, h, NN, DD);
    }
    split_kernel<<<(NN * DD + 255) / 256, 256>>>(h, h_hi, h_lo, NN * DD);

    for (int l = 0; l < LL; ++l) {
        wcat_kernel<<<(KOUT * DD + 255) / 256, 256>>>(bases, w_coe, self_loop, WcT_hi, WcT_lo, l);
        {
            dim3 grid(KOUT / 128, (NN + 127) / 128);
            mma_gemm<<<grid, 256, SMEM_GEMM_TOTAL>>>(h_hi, h_lo, WcT_hi, WcT_lo, nullptr, T, NN, KOUT);
        }
        agginit_kernel<<<(NN * 32 + 255) / 256, 256>>>(T, agg);
        scatter_kernel<<<(EE * 32 + 255) / 256, 256>>>(T, src, dst, etype, nodenorm, agg);
        bnrelu_kernel<<<(NN * DD + 255) / 256, 256>>>(agg,
                                                      bn_gamma + (size_t)l * DD,
                                                      bn_beta  + (size_t)l * DD,
                                                      bn_mean  + (size_t)l * DD,
                                                      bn_var   + (size_t)l * DD,
                                                      h, h_hi, h_lo);
    }

    cudaMemcpyAsync(d_out, h, (size_t)NN * DD * sizeof(float), cudaMemcpyDeviceToDevice);
}

// round 4
// speedup vs baseline: 2.9359x; 1.7505x over previous
#include <cuda_runtime.h>
#include <cuda_bf16.h>
#include <cstdint>
#include <cstddef>

#define NN 50000
#define EE 800000
#define DD 128
#define RR 8
#define BB 4
#define LL 2
#define KCAT 640               // 4 bases * 128 + 128 self-loop
#define BN_EPS 1e-3f
#define ASTRIDE 136            // padded smem row stride (elements)

// ---------------- device scratch ----------------
__device__ float          g_hA[(size_t)NN * DD];
__device__ float          g_hB[(size_t)NN * DD];
__device__ __nv_bfloat16  g_hA_hi[(size_t)NN * DD];
__device__ __nv_bfloat16  g_hA_lo[(size_t)NN * DD];
__device__ __nv_bfloat16  g_hB_hi[(size_t)NN * DD];
__device__ __nv_bfloat16  g_hB_lo[(size_t)NN * DD];
__device__ __nv_bfloat16  g_nf_hi[(size_t)NN * DD];
__device__ __nv_bfloat16  g_nf_lo[(size_t)NN * DD];
__device__ __nv_bfloat16  g_P_hi[(size_t)NN * 512];
__device__ __nv_bfloat16  g_P_lo[(size_t)NN * 512];
__device__ __nv_bfloat16  g_Bcat_hi[(size_t)DD * KCAT];   // [n, k] ld=KCAT
__device__ __nv_bfloat16  g_Bcat_lo[(size_t)DD * KCAT];
__device__ __nv_bfloat16  g_We_hi[(size_t)DD * DD];
__device__ __nv_bfloat16  g_We_lo[(size_t)DD * DD];
__device__ int            g_cnt[(size_t)RR * NN];
__device__ float          g_nodenorm[NN];
__device__ int            g_deg[NN];
__device__ int            g_rowptr[NN + 1];
__device__ int            g_cursor[NN];
__device__ int            g_bsum[256];
__device__ int            g_edges[EE];

// ================= helpers =================
__device__ __forceinline__ uint32_t smem_u32(const void* p) {
    uint32_t a;
    asm("{ .reg .u64 t; cvta.to.shared.u64 t, %1; cvt.u32.u64 %0, t; }" : "=r"(a) : "l"(p));
    return a;
}
__device__ __forceinline__ void ldm_x4(uint32_t* r, uint32_t addr) {
    asm volatile("ldmatrix.sync.aligned.m8n8.x4.shared.b16 {%0,%1,%2,%3}, [%4];"
                 : "=r"(r[0]), "=r"(r[1]), "=r"(r[2]), "=r"(r[3]) : "r"(addr));
}
__device__ __forceinline__ void mma16816(float* d, const uint32_t* a, const uint32_t* b) {
    asm volatile("mma.sync.aligned.m16n8k16.row.col.f32.bf16.bf16.f32 "
                 "{%0,%1,%2,%3}, {%4,%5,%6,%7}, {%8,%9}, {%0,%1,%2,%3};"
                 : "+f"(d[0]), "+f"(d[1]), "+f"(d[2]), "+f"(d[3])
                 : "r"(a[0]), "r"(a[1]), "r"(a[2]), "r"(a[3]), "r"(b[0]), "r"(b[1]));
}
__device__ __forceinline__ void cp_async16(uint32_t d, const void* s, int sz) {
    asm volatile("cp.async.cg.shared.global [%0], [%1], 16, %2;"
                 :: "r"(d), "l"(__cvta_generic_to_global(s)), "r"(sz));
}
__device__ __forceinline__ void split2(float x0, float x1, uint32_t& hi, uint32_t& lo) {
    __nv_bfloat16 h0 = __float2bfloat16(x0), h1 = __float2bfloat16(x1);
    hi = (uint32_t)__bfloat16_as_ushort(h0) | ((uint32_t)__bfloat16_as_ushort(h1) << 16);
    __nv_bfloat16 l0 = __float2bfloat16(x0 - __bfloat162float(h0));
    __nv_bfloat16 l1 = __float2bfloat16(x1 - __bfloat162float(h1));
    lo = (uint32_t)__bfloat16_as_ushort(l0) | ((uint32_t)__bfloat16_as_ushort(l1) << 16);
}
__device__ __forceinline__ void split4(float4 v, uint2& hi, uint2& lo) {
    split2(v.x, v.y, hi.x, lo.x);
    split2(v.z, v.w, hi.y, lo.y);
}

// ================= GEMM (HMMA, virtual-K chunk list, cp.async pipelined) ===========
// C[M, 128] = sum_c A_c[M, 128] @ (B_c[128, 128])^T over chunk list.
// Epilogue: optional bias, optional BN+ReLU; writes fp32 C + bf16 hi/lo split.
struct GemmChunks {
    int n;
    const __nv_bfloat16* A[16];
    const __nv_bfloat16* B[16];
    int lda[16], ldb[16];
};
#define STAGE_ELEMS (2 * 128 * ASTRIDE)                 // A tile + B tile
#define SMEM_GEMM_TOTAL (2 * STAGE_ELEMS * 2)           // bytes (2 stages)

__global__ __launch_bounds__(256)
void mma_gemm(GemmChunks ch,
              const float* __restrict__ bias,
              const float* __restrict__ bn_gamma, const float* __restrict__ bn_beta,
              const float* __restrict__ bn_mean, const float* __restrict__ bn_var,
              float* __restrict__ Cf, __nv_bfloat16* __restrict__ Chi,
              __nv_bfloat16* __restrict__ Clo, int M) {
    extern __shared__ __nv_bfloat16 smem[];
    __shared__ const __nv_bfloat16* sAp[16];
    __shared__ const __nv_bfloat16* sBp[16];
    __shared__ int slda[16], sldb[16];

    const int tid = threadIdx.x;
    const int wid = tid >> 5;
    const int lane = tid & 31;
    const int warp_m = wid >> 2;
    const int warp_n = wid & 3;
    const int m0 = blockIdx.y * 128;

    if (tid == 0) {
        #pragma unroll
        for (int i = 0; i < 16; ++i) {
            sAp[i] = ch.A[i]; sBp[i] = ch.B[i]; slda[i] = ch.lda[i]; sldb[i] = ch.ldb[i];
        }
    }
    __syncthreads();

    auto load_chunk = [&](int c, int st) {
        const __nv_bfloat16* Ac = sAp[c]; const int lda = slda[c];
        const __nv_bfloat16* Bc = sBp[c]; const int ldb = sldb[c];
        __nv_bfloat16* sA = smem + st * STAGE_ELEMS;
        __nv_bfloat16* sB = sA + 128 * ASTRIDE;
        #pragma unroll
        for (int i = 0; i < 8; ++i) {
            int t = tid + i * 256;
            int row = t >> 4, kc = t & 15;
            int gr = m0 + row;
            int ok = (gr < M);
            cp_async16(smem_u32(sA + row * ASTRIDE + kc * 8),
                       Ac + (size_t)(ok ? gr : 0) * lda + kc * 8, ok ? 16 : 0);
        }
        #pragma unroll
        for (int i = 0; i < 8; ++i) {
            int t = tid + i * 256;
            int row = t >> 4, kc = t & 15;
            cp_async16(smem_u32(sB + row * ASTRIDE + kc * 8),
                       Bc + (size_t)row * ldb + kc * 8, 16);
        }
        asm volatile("cp.async.commit_group;" ::: "memory");
    };

    float acc[4][4][4];
    #pragma unroll
    for (int a = 0; a < 4; ++a)
        #pragma unroll
        for (int b = 0; b < 4; ++b)
            #pragma unroll
            for (int c = 0; c < 4; ++c) acc[a][b][c] = 0.f;

    const int a_row_off = (warp_m * 64 + (lane & 15)) * ASTRIDE + ((lane >> 4) << 3);
    const int b_row_off = (warp_n * 32 + (lane & 7) + (((lane >> 4) & 1) << 3)) * ASTRIDE
                          + (((lane >> 3) & 1) << 3);

    auto compute = [&](int st) {
        const uint32_t uA = smem_u32(smem + st * STAGE_ELEMS);
        const uint32_t uB = uA + 128 * ASTRIDE * 2;
        #pragma unroll
        for (int ks = 0; ks < 8; ++ks) {
            const int k0 = ks * 16;
            uint32_t afr[4][4];
            #pragma unroll
            for (int mt = 0; mt < 4; ++mt)
                ldm_x4(afr[mt], uA + (uint32_t)(a_row_off + mt * 16 * ASTRIDE + k0) * 2);
            uint32_t bfr[4][2];
            #pragma unroll
            for (int nt2 = 0; nt2 < 2; ++nt2) {
                uint32_t r[4];
                ldm_x4(r, uB + (uint32_t)(b_row_off + nt2 * 16 * ASTRIDE + k0) * 2);
                bfr[nt2 * 2 + 0][0] = r[0]; bfr[nt2 * 2 + 0][1] = r[1];
                bfr[nt2 * 2 + 1][0] = r[2]; bfr[nt2 * 2 + 1][1] = r[3];
            }
            #pragma unroll
            for (int mt = 0; mt < 4; ++mt)
                #pragma unroll
                for (int nt = 0; nt < 4; ++nt)
                    mma16816(acc[mt][nt], afr[mt], bfr[nt]);
        }
    };

    const int NC = ch.n;
    load_chunk(0, 0);
    for (int c = 0; c < NC; ++c) {
        if (c + 1 < NC) {
            load_chunk(c + 1, (c + 1) & 1);
            asm volatile("cp.async.wait_group 1;" ::: "memory");
        } else {
            asm volatile("cp.async.wait_group 0;" ::: "memory");
        }
        __syncthreads();
        compute(c & 1);
        __syncthreads();
    }

    // ---- epilogue ----
    const bool has_bn = (bn_gamma != nullptr);
    const int mrow = m0 + warp_m * 64 + (lane >> 2);
    const int ncol = warp_n * 32 + 2 * (lane & 3);
    #pragma unroll
    for (int mt = 0; mt < 4; ++mt) {
        #pragma unroll
        for (int half = 0; half < 2; ++half) {
            int gr = mrow + mt * 16 + half * 8;
            if (gr >= M) continue;
            #pragma unroll
            for (int nt = 0; nt < 4; ++nt) {
                int col = ncol + nt * 8;
                float x0 = acc[mt][nt][half * 2 + 0];
                float x1 = acc[mt][nt][half * 2 + 1];
                if (bias) { x0 += __ldg(bias + col); x1 += __ldg(bias + col + 1); }
                if (has_bn) {
                    float g0 = __ldg(bn_gamma + col), g1 = __ldg(bn_gamma + col + 1);
                    float be0 = __ldg(bn_beta + col), be1 = __ldg(bn_beta + col + 1);
                    float mn0 = __ldg(bn_mean + col), mn1 = __ldg(bn_mean + col + 1);
                    float vr0 = __ldg(bn_var + col), vr1 = __ldg(bn_var + col + 1);
                    x0 = fmaxf(g0 * (x0 - mn0) * rsqrtf(vr0 + BN_EPS) + be0, 0.f);
                    x1 = fmaxf(g1 * (x1 - mn1) * rsqrtf(vr1 + BN_EPS) + be1, 0.f);
                }
                float2 o; o.x = x0; o.y = x1;
                *(float2*)(Cf + (size_t)gr * DD + col) = o;
                uint32_t ph, pl;
                split2(x0, x1, ph, pl);
                *(uint32_t*)(Chi + (size_t)gr * DD + col) = ph;
                *(uint32_t*)(Clo + (size_t)gr * DD + col) = pl;
            }
        }
    }
}

// ================= graph prep =================
__global__ __launch_bounds__(256) void count_kernel(const int* __restrict__ dst,
                                                    const int* __restrict__ etype,
                                                    int* __restrict__ cnt) {
    int e = blockIdx.x * blockDim.x + threadIdx.x;
    if (e >= EE) return;
    atomicAdd(&cnt[(size_t)etype[e] * NN + dst[e]], 1);
}

__global__ __launch_bounds__(256) void norm_kernel(const int* __restrict__ cnt,
                                                   float* __restrict__ nodenorm,
                                                   int* __restrict__ deg) {
    int n = blockIdx.x * blockDim.x + threadIdx.x;
    if (n >= NN) return;
    float v = 0.f;
    int d = 0;
    bool found = false;
    #pragma unroll
    for (int r = RR - 1; r >= 0; --r) {
        int c = cnt[(size_t)r * NN + n];
        d += c;
        if (!found && c > 0) { v = 1.0f / (float)c; found = true; }
    }
    nodenorm[n] = v;
    deg[n] = d;
}

__global__ void scan1(const int* __restrict__ deg, int* __restrict__ bsum) {
    __shared__ int s[256];
    int i = blockIdx.x * 256 + threadIdx.x;
    s[threadIdx.x] = (i < NN) ? deg[i] : 0;
    __syncthreads();
    for (int o = 128; o > 0; o >>= 1) {
        if (threadIdx.x < o) s[threadIdx.x] += s[threadIdx.x + o];
        __syncthreads();
    }
    if (threadIdx.x == 0) bsum[blockIdx.x] = s[0];
}
__global__ void scan2(int* __restrict__ bsum, int nb) {
    if (threadIdx.x == 0) {
        int acc = 0;
        for (int i = 0; i < nb; ++i) { int t = bsum[i]; bsum[i] = acc; acc += t; }
    }
}
__global__ void scan3(const int* __restrict__ deg, const int* __restrict__ bsum,
                      int* __restrict__ rowptr, int* __restrict__ cursor) {
    __shared__ int s[256];
    int i = blockIdx.x * 256 + threadIdx.x;
    int v = (i < NN) ? deg[i] : 0;
    s[threadIdx.x] = v;
    __syncthreads();
    for (int o = 1; o < 256; o <<= 1) {
        int t = (threadIdx.x >= o) ? s[threadIdx.x - o] : 0;
        __syncthreads();
        s[threadIdx.x] += t;
        __syncthreads();
    }
    int incl = s[threadIdx.x];
    int off = bsum[blockIdx.x];
    if (i < NN) {
        rowptr[i] = off + incl - v;
        cursor[i] = off + incl - v;
        if (i == NN - 1) rowptr[NN] = off + incl;
    }
}
__global__ __launch_bounds__(256) void fill_kernel(const int* __restrict__ src,
                                                   const int* __restrict__ dst,
                                                   const int* __restrict__ etype,
                                                   int* __restrict__ cursor,
                                                   int* __restrict__ edges) {
    int e = blockIdx.x * blockDim.x + threadIdx.x;
    if (e >= EE) return;
    int p = atomicAdd(&cursor[dst[e]], 1);
    edges[p] = src[e] | (etype[e] << 16);
}

// ================= weight / input prep =================
__global__ __launch_bounds__(256) void wemb_kernel(const float* __restrict__ W,
                                                   __nv_bfloat16* __restrict__ hi,
                                                   __nv_bfloat16* __restrict__ lo) {
    int i = blockIdx.x * blockDim.x + threadIdx.x;
    if (i >= DD * DD) return;
    int n = i >> 7, k = i & 127;
    float v = W[(size_t)k * DD + n];
    __nv_bfloat16 h = __float2bfloat16(v);
    hi[i] = h;
    lo[i] = __float2bfloat16(v - __bfloat162float(h));
}

// Bcat[n, k]: k<512 -> bases[l, k>>7, k&127, n]; else self_loop[l, k-512, n]
__global__ __launch_bounds__(256) void bcat_kernel(const float* __restrict__ bases,
                                                   const float* __restrict__ self_loop,
                                                   __nv_bfloat16* __restrict__ hi,
                                                   __nv_bfloat16* __restrict__ lo, int l) {
    int i = blockIdx.x * blockDim.x + threadIdx.x;
    if (i >= DD * KCAT) return;
    int n = i / KCAT, k = i - n * KCAT;
    float v;
    if (k < 512) {
        int b = k >> 7, d = k & 127;
        v = bases[(size_t)l * BB * DD * DD + (size_t)b * DD * DD + (size_t)d * DD + n];
    } else {
        v = self_loop[(size_t)l * DD * DD + (size_t)(k - 512) * DD + n];
    }
    __nv_bfloat16 h = __float2bfloat16(v);
    hi[i] = h;
    lo[i] = __float2bfloat16(v - __bfloat162float(h));
}

// split fp32 [N,128] -> bf16 hi/lo, vectorized
__global__ __launch_bounds__(256) void split4_kernel(const float* __restrict__ x,
                                                     __nv_bfloat16* __restrict__ hi,
                                                     __nv_bfloat16* __restrict__ lo) {
    int i = blockIdx.x * blockDim.x + threadIdx.x;
    if (i >= NN * 32) return;
    float4 v = ((const float4*)x)[i];
    uint2 ph, pl;
    split4(v, ph, pl);
    ((uint2*)hi)[i] = ph;
    ((uint2*)lo)[i] = pl;
}

// ================= gather: P_b[dst] = norm[dst] * sum_in w_coe[r,b] * h[src] =========
__global__ __launch_bounds__(256) void gather_kernel(const int* __restrict__ rowptr,
                                                     const int* __restrict__ edges,
                                                     const float* __restrict__ h,
                                                     const float* __restrict__ nodenorm,
                                                     const float* __restrict__ w_coe, int l,
                                                     __nv_bfloat16* __restrict__ Phi,
                                                     __nv_bfloat16* __restrict__ Plo) {
    __shared__ float swc[RR * BB];
    if (threadIdx.x < RR * BB) swc[threadIdx.x] = w_coe[l * RR * BB + threadIdx.x];
    __syncthreads();

    int gw = (blockIdx.x * 256 + threadIdx.x) >> 5;
    int lane = threadIdx.x & 31;
    if (gw >= NN) return;

    float4 a0 = make_float4(0.f, 0.f, 0.f, 0.f), a1 = a0, a2 = a0, a3 = a0;
    int beg = rowptr[gw], end = rowptr[gw + 1];
    for (int i = beg; i < end; ++i) {
        int ev = edges[i];
        int s = ev & 0xFFFF;
        int r = ev >> 16;
        float4 v = *(const float4*)(h + (size_t)s * DD + lane * 4);
        float w0 = swc[r * 4 + 0], w1 = swc[r * 4 + 1];
        float w2 = swc[r * 4 + 2], w3 = swc[r * 4 + 3];
        a0.x += w0 * v.x; a0.y += w0 * v.y; a0.z += w0 * v.z; a0.w += w0 * v.w;
        a1.x += w1 * v.x; a1.y += w1 * v.y; a1.z += w1 * v.z; a1.w += w1 * v.w;
        a2.x += w2 * v.x; a2.y += w2 * v.y; a2.z += w2 * v.z; a2.w += w2 * v.w;
        a3.x += w3 * v.x; a3.y += w3 * v.y; a3.z += w3 * v.z; a3.w += w3 * v.w;
    }
    float nrm = nodenorm[gw];
    a0.x *= nrm; a0.y *= nrm; a0.z *= nrm; a0.w *= nrm;
    a1.x *= nrm; a1.y *= nrm; a1.z *= nrm; a1.w *= nrm;
    a2.x *= nrm; a2.y *= nrm; a2.z *= nrm; a2.w *= nrm;
    a3.x *= nrm; a3.y *= nrm; a3.z *= nrm; a3.w *= nrm;

    uint2 ph, pl;
    size_t base = (size_t)gw * 512 + lane * 4;
    split4(a0, ph, pl);
    *(uint2*)(Phi + base) = ph;           *(uint2*)(Plo + base) = pl;
    split4(a1, ph, pl);
    *(uint2*)(Phi + base + 128) = ph;     *(uint2*)(Plo + base + 128) = pl;
    split4(a2, ph, pl);
    *(uint2*)(Phi + base + 256) = ph;     *(uint2*)(Plo + base + 256) = pl;
    split4(a3, ph, pl);
    *(uint2*)(Phi + base + 384) = ph;     *(uint2*)(Plo + base + 384) = pl;
}

// ================= launcher =================
extern "C" void kernel_launch(void* const* d_in, const int* in_sizes, int n_in,
                              void* d_out, int out_size) {
    const float* node_feat = (const float*)d_in[0];
    const float* W_emb     = (const float*)d_in[1];
    const float* b_emb     = (const float*)d_in[2];
    const float* bases     = (const float*)d_in[3];
    const float* w_coe     = (const float*)d_in[4];
    const float* self_loop = (const float*)d_in[5];
    const float* bn_gamma  = (const float*)d_in[6];
    const float* bn_beta   = (const float*)d_in[7];
    const float* bn_mean   = (const float*)d_in[8];
    const float* bn_var    = (const float*)d_in[9];
    const int*   src       = (const int*)d_in[10];
    const int*   dst       = (const int*)d_in[11];
    const int*   etype     = (const int*)d_in[12];

    float *hA, *hB, *nodenorm;
    __nv_bfloat16 *hA_hi, *hA_lo, *hB_hi, *hB_lo, *nf_hi, *nf_lo;
    __nv_bfloat16 *P_hi, *P_lo, *Bc_hi, *Bc_lo, *We_hi, *We_lo;
    int *cnt, *deg, *rowptr, *cursor, *bsum, *edges;
    cudaGetSymbolAddress((void**)&hA, g_hA);
    cudaGetSymbolAddress((void**)&hB, g_hB);
    cudaGetSymbolAddress((void**)&hA_hi, g_hA_hi);
    cudaGetSymbolAddress((void**)&hA_lo, g_hA_lo);
    cudaGetSymbolAddress((void**)&hB_hi, g_hB_hi);
    cudaGetSymbolAddress((void**)&hB_lo, g_hB_lo);
    cudaGetSymbolAddress((void**)&nf_hi, g_nf_hi);
    cudaGetSymbolAddress((void**)&nf_lo, g_nf_lo);
    cudaGetSymbolAddress((void**)&P_hi, g_P_hi);
    cudaGetSymbolAddress((void**)&P_lo, g_P_lo);
    cudaGetSymbolAddress((void**)&Bc_hi, g_Bcat_hi);
    cudaGetSymbolAddress((void**)&Bc_lo, g_Bcat_lo);
    cudaGetSymbolAddress((void**)&We_hi, g_We_hi);
    cudaGetSymbolAddress((void**)&We_lo, g_We_lo);
    cudaGetSymbolAddress((void**)&cnt, g_cnt);
    cudaGetSymbolAddress((void**)&nodenorm, g_nodenorm);
    cudaGetSymbolAddress((void**)&deg, g_deg);
    cudaGetSymbolAddress((void**)&rowptr, g_rowptr);
    cudaGetSymbolAddress((void**)&cursor, g_cursor);
    cudaGetSymbolAddress((void**)&bsum, g_bsum);
    cudaGetSymbolAddress((void**)&edges, g_edges);

    cudaFuncSetAttribute(mma_gemm, cudaFuncAttributeMaxDynamicSharedMemorySize, SMEM_GEMM_TOTAL);

    const int NB = (NN + 255) / 256;   // 196

    // graph prep
    cudaMemsetAsync(cnt, 0, (size_t)RR * NN * sizeof(int));
    count_kernel<<<(EE + 255) / 256, 256>>>(dst, etype, cnt);
    norm_kernel<<<NB, 256>>>(cnt, nodenorm, deg);
    scan1<<<NB, 256>>>(deg, bsum);
    scan2<<<1, 32>>>(bsum, NB);
    scan3<<<NB, 256>>>(deg, bsum, rowptr, cursor);
    fill_kernel<<<(EE + 255) / 256, 256>>>(src, dst, etype, cursor, edges);

    // weight / input prep
    wemb_kernel<<<(DD * DD + 255) / 256, 256>>>(W_emb, We_hi, We_lo);
    split4_kernel<<<(NN * 32 + 255) / 256, 256>>>(node_feat, nf_hi, nf_lo);

    dim3 ggrid(1, (NN + 127) / 128);

    // embedding GEMM: hA = node_feat @ W_emb + b_emb  (+ fused bf16 split)
    {
        GemmChunks ce = {};
        ce.n = 3;
        ce.A[0] = nf_hi; ce.A[1] = nf_lo; ce.A[2] = nf_hi;
        ce.B[0] = We_hi; ce.B[1] = We_hi; ce.B[2] = We_lo;
        for (int i = 0; i < 3; ++i) { ce.lda[i] = DD; ce.ldb[i] = DD; }
        mma_gemm<<<ggrid, 256, SMEM_GEMM_TOTAL>>>(ce, b_emb, nullptr, nullptr, nullptr, nullptr,
                                                  hA, hA_hi, hA_lo, NN);
    }

    for (int l = 0; l < LL; ++l) {
        float* hin = l ? hB : hA;
        __nv_bfloat16* hin_hi = l ? hB_hi : hA_hi;
        __nv_bfloat16* hin_lo = l ? hB_lo : hA_lo;
        float* hout = l ? hA : hB;
        __nv_bfloat16* hout_hi = l ? hA_hi : hB_hi;
        __nv_bfloat16* hout_lo = l ? hA_lo : hB_lo;

        bcat_kernel<<<(DD * KCAT + 255) / 256, 256>>>(bases, self_loop, Bc_hi, Bc_lo, l);
        gather_kernel<<<(NN * 32 + 255) / 256, 256>>>(rowptr, edges, hin, nodenorm,
                                                      w_coe, l, P_hi, P_lo);
        GemmChunks cl = {};
        cl.n = 15;
        int c = 0;
        for (int t = 0; t < 3; ++t) {
            const __nv_bfloat16* Pa = (t == 1) ? P_lo : P_hi;
            const __nv_bfloat16* ha = (t == 1) ? hin_lo : hin_hi;
            const __nv_bfloat16* Bb = (t == 2) ? Bc_lo : Bc_hi;
            for (int kc = 0; kc < 5; ++kc) {
                if (kc < 4) { cl.A[c] = Pa + kc * 128; cl.lda[c] = 512; }
                else        { cl.A[c] = ha;            cl.lda[c] = DD;  }
                cl.B[c] = Bb + kc * 128;
                cl.ldb[c] = KCAT;
                ++c;
            }
        }
        mma_gemm<<<ggrid, 256, SMEM_GEMM_TOTAL>>>(cl, nullptr,
                                                  bn_gamma + (size_t)l * DD,
                                                  bn_beta  + (size_t)l * DD,
                                                  bn_mean  + (size_t)l * DD,
                                                  bn_var   + (size_t)l * DD,
                                                  hout, hout_hi, hout_lo, NN);
    }

    cudaMemcpyAsync(d_out, hA, (size_t)NN * DD * sizeof(float), cudaMemcpyDeviceToDevice);
}

// round 5
// speedup vs baseline: 3.2776x; 1.1164x over previous
#include <cuda_runtime.h>
#include <cuda_bf16.h>
#include <cstdint>
#include <cstddef>

#define NN 50000
#define EE 800000
#define DD 128
#define RR 8
#define BB 4
#define LL 2
#define KCAT 640               // 4 bases * 128 + 128 self-loop
#define BN_EPS 1e-3f

#define KCH 64                 // k-chunk depth
#define RS 72                  // smem row stride (elements), 144B: conflict-free ldsm
#define TILE_E (128 * RS)      // 9216 elements per tile
#define STAGE_E (4 * TILE_E)   // A_hi, A_lo, B_hi, B_lo
#define SMEM_GEMM_TOTAL (2 * STAGE_E * 2)   // bytes = 147456

// ---------------- device scratch ----------------
__device__ float          g_hA[(size_t)NN * DD];
__device__ float          g_hB[(size_t)NN * DD];
__device__ __nv_bfloat16  g_hA_hi[(size_t)NN * DD];
__device__ __nv_bfloat16  g_hA_lo[(size_t)NN * DD];
__device__ __nv_bfloat16  g_hB_hi[(size_t)NN * DD];
__device__ __nv_bfloat16  g_hB_lo[(size_t)NN * DD];
__device__ __nv_bfloat16  g_nf_hi[(size_t)NN * DD];
__device__ __nv_bfloat16  g_nf_lo[(size_t)NN * DD];
__device__ __nv_bfloat16  g_P_hi[(size_t)NN * 512];
__device__ __nv_bfloat16  g_P_lo[(size_t)NN * 512];
__device__ __nv_bfloat16  g_Bc_hi[2][(size_t)DD * KCAT];   // [n, k] ld=KCAT, per layer
__device__ __nv_bfloat16  g_Bc_lo[2][(size_t)DD * KCAT];
__device__ __nv_bfloat16  g_We_hi[(size_t)DD * DD];
__device__ __nv_bfloat16  g_We_lo[(size_t)DD * DD];
__device__ int            g_cnt[(size_t)RR * NN];
__device__ float          g_nodenorm[NN];
__device__ int            g_deg[NN];
__device__ int            g_rowptr[NN + 1];
__device__ int            g_cursor[NN];
__device__ int            g_bsum[256];
__device__ int            g_edges[EE];

// ================= helpers =================
__device__ __forceinline__ uint32_t smem_u32(const void* p) {
    uint32_t a;
    asm("{ .reg .u64 t; cvta.to.shared.u64 t, %1; cvt.u32.u64 %0, t; }" : "=r"(a) : "l"(p));
    return a;
}
__device__ __forceinline__ void ldm_x4(uint32_t* r, uint32_t addr) {
    asm volatile("ldmatrix.sync.aligned.m8n8.x4.shared.b16 {%0,%1,%2,%3}, [%4];"
                 : "=r"(r[0]), "=r"(r[1]), "=r"(r[2]), "=r"(r[3]) : "r"(addr));
}
__device__ __forceinline__ void mma16816(float* d, const uint32_t* a, const uint32_t* b) {
    asm volatile("mma.sync.aligned.m16n8k16.row.col.f32.bf16.bf16.f32 "
                 "{%0,%1,%2,%3}, {%4,%5,%6,%7}, {%8,%9}, {%0,%1,%2,%3};"
                 : "+f"(d[0]), "+f"(d[1]), "+f"(d[2]), "+f"(d[3])
                 : "r"(a[0]), "r"(a[1]), "r"(a[2]), "r"(a[3]), "r"(b[0]), "r"(b[1]));
}
__device__ __forceinline__ void cp_async16(uint32_t d, const void* s, int sz) {
    asm volatile("cp.async.cg.shared.global [%0], [%1], 16, %2;"
                 :: "r"(d), "l"(__cvta_generic_to_global(s)), "r"(sz));
}
__device__ __forceinline__ void split2(float x0, float x1, uint32_t& hi, uint32_t& lo) {
    __nv_bfloat16 h0 = __float2bfloat16(x0), h1 = __float2bfloat16(x1);
    hi = (uint32_t)__bfloat16_as_ushort(h0) | ((uint32_t)__bfloat16_as_ushort(h1) << 16);
    __nv_bfloat16 l0 = __float2bfloat16(x0 - __bfloat162float(h0));
    __nv_bfloat16 l1 = __float2bfloat16(x1 - __bfloat162float(h1));
    lo = (uint32_t)__bfloat16_as_ushort(l0) | ((uint32_t)__bfloat16_as_ushort(l1) << 16);
}
__device__ __forceinline__ void split4(float4 v, uint2& hi, uint2& lo) {
    split2(v.x, v.y, hi.x, lo.x);
    split2(v.z, v.w, hi.y, lo.y);
}

// ================= GEMM (HMMA, fused 3-term split per k-chunk) ===========
// C[M,128] = sum_chunks (A_hi+A_lo)[:,64] @ ((B_hi+B_lo)[:,64])^T   (3 term passes)
struct Chunk { const __nv_bfloat16 *Ahi, *Alo, *Bhi, *Blo; int lda, ldb; };
struct GemmChunks { int n; Chunk c[10]; };

__global__ __launch_bounds__(256)
void mma_gemm(GemmChunks ch,
              const float* __restrict__ bias,
              const float* __restrict__ bn_gamma, const float* __restrict__ bn_beta,
              const float* __restrict__ bn_mean, const float* __restrict__ bn_var,
              float* __restrict__ Cf, __nv_bfloat16* __restrict__ Chi,
              __nv_bfloat16* __restrict__ Clo, int M) {
    extern __shared__ __nv_bfloat16 smem[];
    const int tid = threadIdx.x;
    const int wid = tid >> 5;
    const int lane = tid & 31;
    const int warp_m = wid >> 2;
    const int warp_n = wid & 3;
    const int m0 = blockIdx.y * 128;

    auto load_chunk = [&](int c, int st) {
        const Chunk ck = ch.c[c];
        __nv_bfloat16* s0 = smem + st * STAGE_E;
        #pragma unroll
        for (int i = 0; i < 4; ++i) {
            int t = tid + i * 256;          // 0..1023
            int row = t >> 3, kc = t & 7;   // kc: 8B-elem groups of 8 bf16
            int gr = m0 + row;
            int ok = (gr < M);
            size_t ga = (size_t)(ok ? gr : 0);
            uint32_t so = smem_u32(s0 + row * RS + kc * 8);
            cp_async16(so,                      ck.Ahi + ga * ck.lda + kc * 8, ok ? 16 : 0);
            cp_async16(so + TILE_E * 2,         ck.Alo + ga * ck.lda + kc * 8, ok ? 16 : 0);
            cp_async16(so + TILE_E * 4,         ck.Bhi + (size_t)row * ck.ldb + kc * 8, 16);
            cp_async16(so + TILE_E * 6,         ck.Blo + (size_t)row * ck.ldb + kc * 8, 16);
        }
        asm volatile("cp.async.commit_group;" ::: "memory");
    };

    float acc[4][4][4];
    #pragma unroll
    for (int a = 0; a < 4; ++a)
        #pragma unroll
        for (int b = 0; b < 4; ++b)
            #pragma unroll
            for (int c = 0; c < 4; ++c) acc[a][b][c] = 0.f;

    const int a_row_off = (warp_m * 64 + (lane & 15)) * RS + ((lane >> 4) << 3);
    const int b_row_off = (warp_n * 32 + (lane & 7) + (((lane >> 4) & 1) << 3)) * RS
                          + (((lane >> 3) & 1) << 3);

    auto compute = [&](int st) {
        const uint32_t ub = smem_u32(smem + st * STAGE_E);
        // term passes: (A_hi,B_hi), (A_lo,B_hi), (A_hi,B_lo)
        const uint32_t ta[3] = {0u, (uint32_t)TILE_E * 2u, 0u};
        const uint32_t tb[3] = {(uint32_t)TILE_E * 4u, (uint32_t)TILE_E * 4u, (uint32_t)TILE_E * 6u};
        #pragma unroll
        for (int p = 0; p < 3; ++p) {
            const uint32_t uA = ub + ta[p];
            const uint32_t uB = ub + tb[p];
            #pragma unroll
            for (int ks = 0; ks < 4; ++ks) {
                const int k0 = ks * 16;
                uint32_t afr[4][4];
                #pragma unroll
                for (int mt = 0; mt < 4; ++mt)
                    ldm_x4(afr[mt], uA + (uint32_t)(a_row_off + mt * 16 * RS + k0) * 2);
                uint32_t bfr[4][2];
                #pragma unroll
                for (int nt2 = 0; nt2 < 2; ++nt2) {
                    uint32_t r[4];
                    ldm_x4(r, uB + (uint32_t)(b_row_off + nt2 * 16 * RS + k0) * 2);
                    bfr[nt2 * 2 + 0][0] = r[0]; bfr[nt2 * 2 + 0][1] = r[1];
                    bfr[nt2 * 2 + 1][0] = r[2]; bfr[nt2 * 2 + 1][1] = r[3];
                }
                #pragma unroll
                for (int mt = 0; mt < 4; ++mt)
                    #pragma unroll
                    for (int nt = 0; nt < 4; ++nt)
                        mma16816(acc[mt][nt], afr[mt], bfr[nt]);
            }
        }
    };

    const int NC = ch.n;
    load_chunk(0, 0);
    for (int c = 0; c < NC; ++c) {
        if (c + 1 < NC) {
            load_chunk(c + 1, (c + 1) & 1);
            asm volatile("cp.async.wait_group 1;" ::: "memory");
        } else {
            asm volatile("cp.async.wait_group 0;" ::: "memory");
        }
        __syncthreads();
        compute(c & 1);
        __syncthreads();
    }

    // ---- epilogue: bias / BN+ReLU, fp32 out + fused bf16 hi/lo split ----
    const bool has_bn = (bn_gamma != nullptr);
    const int mrow = m0 + warp_m * 64 + (lane >> 2);
    const int ncol = warp_n * 32 + 2 * (lane & 3);
    #pragma unroll
    for (int mt = 0; mt < 4; ++mt) {
        #pragma unroll
        for (int half = 0; half < 2; ++half) {
            int gr = mrow + mt * 16 + half * 8;
            if (gr >= M) continue;
            #pragma unroll
            for (int nt = 0; nt < 4; ++nt) {
                int col = ncol + nt * 8;
                float x0 = acc[mt][nt][half * 2 + 0];
                float x1 = acc[mt][nt][half * 2 + 1];
                if (bias) { x0 += __ldg(bias + col); x1 += __ldg(bias + col + 1); }
                if (has_bn) {
                    float g0 = __ldg(bn_gamma + col), g1 = __ldg(bn_gamma + col + 1);
                    float be0 = __ldg(bn_beta + col), be1 = __ldg(bn_beta + col + 1);
                    float mn0 = __ldg(bn_mean + col), mn1 = __ldg(bn_mean + col + 1);
                    float vr0 = __ldg(bn_var + col), vr1 = __ldg(bn_var + col + 1);
                    x0 = fmaxf(g0 * (x0 - mn0) * rsqrtf(vr0 + BN_EPS) + be0, 0.f);
                    x1 = fmaxf(g1 * (x1 - mn1) * rsqrtf(vr1 + BN_EPS) + be1, 0.f);
                }
                float2 o; o.x = x0; o.y = x1;
                *(float2*)(Cf + (size_t)gr * DD + col) = o;
                uint32_t ph, pl;
                split2(x0, x1, ph, pl);
                *(uint32_t*)(Chi + (size_t)gr * DD + col) = ph;
                *(uint32_t*)(Clo + (size_t)gr * DD + col) = pl;
            }
        }
    }
}

// ================= fused prep (block-range dispatch) =================
// blocks [0,6250): split node_feat -> nf_hi/lo
// blocks [6250,9375): count (atomics into cnt)
// blocks [9375,9439): WembT split
// blocks [9439,9759): Bcat layer 0
// blocks [9759,10079): Bcat layer 1
#define PB_SPLIT 6250
#define PB_COUNT (PB_SPLIT + 3125)
#define PB_WEMB  (PB_COUNT + 64)
#define PB_BC0   (PB_WEMB + 320)
#define PB_BC1   (PB_BC0 + 320)

__global__ __launch_bounds__(256)
void prep_kernel(const float* __restrict__ node_feat, const float* __restrict__ W_emb,
                 const float* __restrict__ bases, const float* __restrict__ self_loop,
                 const int* __restrict__ dst, const int* __restrict__ etype,
                 int* __restrict__ cnt,
                 __nv_bfloat16* __restrict__ nf_hi, __nv_bfloat16* __restrict__ nf_lo,
                 __nv_bfloat16* __restrict__ We_hi, __nv_bfloat16* __restrict__ We_lo,
                 __nv_bfloat16* __restrict__ Bc0_hi, __nv_bfloat16* __restrict__ Bc0_lo,
                 __nv_bfloat16* __restrict__ Bc1_hi, __nv_bfloat16* __restrict__ Bc1_lo) {
    int b = blockIdx.x;
    int t = threadIdx.x;
    if (b < PB_SPLIT) {
        int i = b * 256 + t;                     // over NN*32 float4s
        float4 v = ((const float4*)node_feat)[i];
        uint2 ph, pl;
        split4(v, ph, pl);
        ((uint2*)nf_hi)[i] = ph;
        ((uint2*)nf_lo)[i] = pl;
    } else if (b < PB_COUNT) {
        int e = (b - PB_SPLIT) * 256 + t;
        if (e < EE) atomicAdd(&cnt[(size_t)etype[e] * NN + dst[e]], 1);
    } else if (b < PB_WEMB) {
        int i = (b - PB_COUNT) * 256 + t;        // over DD*DD
        int n = i >> 7, k = i & 127;
        float v = W_emb[(size_t)k * DD + n];
        __nv_bfloat16 h = __float2bfloat16(v);
        We_hi[i] = h;
        We_lo[i] = __float2bfloat16(v - __bfloat162float(h));
    } else {
        int l = (b < PB_BC0) ? 0 : 1;
        int i = (b - (l ? PB_BC0 : PB_WEMB)) * 256 + t;   // over DD*KCAT
        int n = i / KCAT, k = i - n * KCAT;
        float v;
        if (k < 512) {
            int bb = k >> 7, d = k & 127;
            v = bases[(size_t)l * BB * DD * DD + (size_t)bb * DD * DD + (size_t)d * DD + n];
        } else {
            v = self_loop[(size_t)l * DD * DD + (size_t)(k - 512) * DD + n];
        }
        __nv_bfloat16 h = __float2bfloat16(v);
        __nv_bfloat16 lo = __float2bfloat16(v - __bfloat162float(h));
        if (l == 0) { Bc0_hi[i] = h; Bc0_lo[i] = lo; }
        else        { Bc1_hi[i] = h; Bc1_lo[i] = lo; }
    }
}

__global__ __launch_bounds__(256) void zero_cnt_kernel(int4* __restrict__ cnt4) {
    int i = blockIdx.x * 256 + threadIdx.x;
    if (i < RR * NN / 4) cnt4[i] = make_int4(0, 0, 0, 0);
}

// norm + deg + per-block deg sum
__global__ __launch_bounds__(256) void normd_kernel(const int* __restrict__ cnt,
                                                    float* __restrict__ nodenorm,
                                                    int* __restrict__ deg,
                                                    int* __restrict__ bsum) {
    __shared__ int s[256];
    int n = blockIdx.x * 256 + threadIdx.x;
    int d = 0;
    if (n < NN) {
        float v = 0.f;
        bool found = false;
        #pragma unroll
        for (int r = RR - 1; r >= 0; --r) {
            int c = cnt[(size_t)r * NN + n];
            d += c;
            if (!found && c > 0) { v = 1.0f / (float)c; found = true; }
        }
        nodenorm[n] = v;
        deg[n] = d;
    }
    s[threadIdx.x] = d;
    __syncthreads();
    for (int o = 128; o > 0; o >>= 1) {
        if (threadIdx.x < o) s[threadIdx.x] += s[threadIdx.x + o];
        __syncthreads();
    }
    if (threadIdx.x == 0) bsum[blockIdx.x] = s[0];
}

// parallel exclusive scan of block sums (nb <= 256)
__global__ void scan2p(int* __restrict__ bsum, int nb) {
    __shared__ int s[256];
    int t = threadIdx.x;
    int v = (t < nb) ? bsum[t] : 0;
    s[t] = v;
    __syncthreads();
    for (int o = 1; o < 256; o <<= 1) {
        int u = (t >= o) ? s[t - o] : 0;
        __syncthreads();
        s[t] += u;
        __syncthreads();
    }
    if (t < nb) bsum[t] = s[t] - v;
}

__global__ void scan3(const int* __restrict__ deg, const int* __restrict__ bsum,
                      int* __restrict__ rowptr, int* __restrict__ cursor) {
    __shared__ int s[256];
    int i = blockIdx.x * 256 + threadIdx.x;
    int v = (i < NN) ? deg[i] : 0;
    s[threadIdx.x] = v;
    __syncthreads();
    for (int o = 1; o < 256; o <<= 1) {
        int t = (threadIdx.x >= o) ? s[threadIdx.x - o] : 0;
        __syncthreads();
        s[threadIdx.x] += t;
        __syncthreads();
    }
    int incl = s[threadIdx.x];
    int off = bsum[blockIdx.x];
    if (i < NN) {
        rowptr[i] = off + incl - v;
        cursor[i] = off + incl - v;
        if (i == NN - 1) rowptr[NN] = off + incl;
    }
}

__global__ __launch_bounds__(256) void fill_kernel(const int* __restrict__ src,
                                                   const int* __restrict__ dst,
                                                   const int* __restrict__ etype,
                                                   int* __restrict__ cursor,
                                                   int* __restrict__ edges) {
    int e = blockIdx.x * blockDim.x + threadIdx.x;
    if (e >= EE) return;
    int p = atomicAdd(&cursor[dst[e]], 1);
    edges[p] = src[e] | (etype[e] << 16);
}

// ================= gather: P_b[dst] = norm[dst] * sum_in w_coe[r,b] * h[src] =========
__global__ __launch_bounds__(256) void gather_kernel(const int* __restrict__ rowptr,
                                                     const int* __restrict__ edges,
                                                     const float* __restrict__ h,
                                                     const float* __restrict__ nodenorm,
                                                     const float* __restrict__ w_coe, int l,
                                                     __nv_bfloat16* __restrict__ Phi,
                                                     __nv_bfloat16* __restrict__ Plo) {
    __shared__ float swc[RR * BB];
    if (threadIdx.x < RR * BB) swc[threadIdx.x] = w_coe[l * RR * BB + threadIdx.x];
    __syncthreads();

    int gw = (blockIdx.x * 256 + threadIdx.x) >> 5;
    int lane = threadIdx.x & 31;
    if (gw >= NN) return;

    float4 a0 = make_float4(0.f, 0.f, 0.f, 0.f), a1 = a0, a2 = a0, a3 = a0;
    const int beg = rowptr[gw], end = rowptr[gw + 1];

    auto accum = [&](int ev, float4 v) {
        int r = ev >> 16;
        float w0 = swc[r * 4 + 0], w1 = swc[r * 4 + 1];
        float w2 = swc[r * 4 + 2], w3 = swc[r * 4 + 3];
        a0.x += w0 * v.x; a0.y += w0 * v.y; a0.z += w0 * v.z; a0.w += w0 * v.w;
        a1.x += w1 * v.x; a1.y += w1 * v.y; a1.z += w1 * v.z; a1.w += w1 * v.w;
        a2.x += w2 * v.x; a2.y += w2 * v.y; a2.z += w2 * v.z; a2.w += w2 * v.w;
        a3.x += w3 * v.x; a3.y += w3 * v.y; a3.z += w3 * v.z; a3.w += w3 * v.w;
    };

    int i = beg;
    for (; i + 4 <= end; i += 4) {
        int e0 = edges[i], e1 = edges[i + 1], e2 = edges[i + 2], e3 = edges[i + 3];
        float4 v0 = *(const float4*)(h + (size_t)(e0 & 0xFFFF) * DD + lane * 4);
        float4 v1 = *(const float4*)(h + (size_t)(e1 & 0xFFFF) * DD + lane * 4);
        float4 v2 = *(const float4*)(h + (size_t)(e2 & 0xFFFF) * DD + lane * 4);
        float4 v3 = *(const float4*)(h + (size_t)(e3 & 0xFFFF) * DD + lane * 4);
        accum(e0, v0); accum(e1, v1); accum(e2, v2); accum(e3, v3);
    }
    for (; i < end; ++i) {
        int ev = edges[i];
        float4 v = *(const float4*)(h + (size_t)(ev & 0xFFFF) * DD + lane * 4);
        accum(ev, v);
    }

    float nrm = nodenorm[gw];
    a0.x *= nrm; a0.y *= nrm; a0.z *= nrm; a0.w *= nrm;
    a1.x *= nrm; a1.y *= nrm; a1.z *= nrm; a1.w *= nrm;
    a2.x *= nrm; a2.y *= nrm; a2.z *= nrm; a2.w *= nrm;
    a3.x *= nrm; a3.y *= nrm; a3.z *= nrm; a3.w *= nrm;

    uint2 ph, pl;
    size_t base = (size_t)gw * 512 + lane * 4;
    split4(a0, ph, pl);
    *(uint2*)(Phi + base) = ph;           *(uint2*)(Plo + base) = pl;
    split4(a1, ph, pl);
    *(uint2*)(Phi + base + 128) = ph;     *(uint2*)(Plo + base + 128) = pl;
    split4(a2, ph, pl);
    *(uint2*)(Phi + base + 256) = ph;     *(uint2*)(Plo + base + 256) = pl;
    split4(a3, ph, pl);
    *(uint2*)(Phi + base + 384) = ph;     *(uint2*)(Plo + base + 384) = pl;
}

// ================= launcher =================
extern "C" void kernel_launch(void* const* d_in, const int* in_sizes, int n_in,
                              void* d_out, int out_size) {
    const float* node_feat = (const float*)d_in[0];
    const float* W_emb     = (const float*)d_in[1];
    const float* b_emb     = (const float*)d_in[2];
    const float* bases     = (const float*)d_in[3];
    const float* w_coe     = (const float*)d_in[4];
    const float* self_loop = (const float*)d_in[5];
    const float* bn_gamma  = (const float*)d_in[6];
    const float* bn_beta   = (const float*)d_in[7];
    const float* bn_mean   = (const float*)d_in[8];
    const float* bn_var    = (const float*)d_in[9];
    const int*   src       = (const int*)d_in[10];
    const int*   dst       = (const int*)d_in[11];
    const int*   etype     = (const int*)d_in[12];

    float *hA, *hB, *nodenorm;
    __nv_bfloat16 *hA_hi, *hA_lo, *hB_hi, *hB_lo, *nf_hi, *nf_lo;
    __nv_bfloat16 *P_hi, *P_lo, *Bc_hi, *Bc_lo, *We_hi, *We_lo;
    int *cnt, *deg, *rowptr, *cursor, *bsum, *edges;
    cudaGetSymbolAddress((void**)&hA, g_hA);
    cudaGetSymbolAddress((void**)&hB, g_hB);
    cudaGetSymbolAddress((void**)&hA_hi, g_hA_hi);
    cudaGetSymbolAddress((void**)&hA_lo, g_hA_lo);
    cudaGetSymbolAddress((void**)&hB_hi, g_hB_hi);
    cudaGetSymbolAddress((void**)&hB_lo, g_hB_lo);
    cudaGetSymbolAddress((void**)&nf_hi, g_nf_hi);
    cudaGetSymbolAddress((void**)&nf_lo, g_nf_lo);
    cudaGetSymbolAddress((void**)&P_hi, g_P_hi);
    cudaGetSymbolAddress((void**)&P_lo, g_P_lo);
    cudaGetSymbolAddress((void**)&Bc_hi, g_Bc_hi);
    cudaGetSymbolAddress((void**)&Bc_lo, g_Bc_lo);
    cudaGetSymbolAddress((void**)&We_hi, g_We_hi);
    cudaGetSymbolAddress((void**)&We_lo, g_We_lo);
    cudaGetSymbolAddress((void**)&cnt, g_cnt);
    cudaGetSymbolAddress((void**)&nodenorm, g_nodenorm);
    cudaGetSymbolAddress((void**)&deg, g_deg);
    cudaGetSymbolAddress((void**)&rowptr, g_rowptr);
    cudaGetSymbolAddress((void**)&cursor, g_cursor);
    cudaGetSymbolAddress((void**)&bsum, g_bsum);
    cudaGetSymbolAddress((void**)&edges, g_edges);

    cudaFuncSetAttribute(mma_gemm, cudaFuncAttributeMaxDynamicSharedMemorySize, SMEM_GEMM_TOTAL);

    const int NB = (NN + 255) / 256;   // 196
    dim3 ggrid(1, (NN + 127) / 128);

    // [0] zero counts
    zero_cnt_kernel<<<(RR * NN / 4 + 255) / 256, 256>>>((int4*)cnt);
    // [1] fused prep: split(nf) + count + WembT + Bcat(l=0,1)
    prep_kernel<<<PB_BC1, 256>>>(node_feat, W_emb, bases, self_loop, dst, etype, cnt,
                                 nf_hi, nf_lo, We_hi, We_lo,
                                 &Bc_hi[0], &Bc_lo[0],
                                 &Bc_hi[(size_t)DD * KCAT], &Bc_lo[(size_t)DD * KCAT]);
    // [2] norm + deg + block sums
    normd_kernel<<<NB, 256>>>(cnt, nodenorm, deg, bsum);
    // [3] scan of block sums
    scan2p<<<1, 256>>>(bsum, NB);
    // [4] rowptr/cursor
    scan3<<<NB, 256>>>(deg, bsum, rowptr, cursor);
    // [5] embedding GEMM (profile target): hA = nf @ W_emb + b_emb
    {
        GemmChunks ce = {};
        ce.n = 2;
        for (int c = 0; c < 2; ++c) {
            ce.c[c].Ahi = nf_hi + c * KCH; ce.c[c].Alo = nf_lo + c * KCH; ce.c[c].lda = DD;
            ce.c[c].Bhi = We_hi + c * KCH; ce.c[c].Blo = We_lo + c * KCH; ce.c[c].ldb = DD;
        }
        mma_gemm<<<ggrid, 256, SMEM_GEMM_TOTAL>>>(ce, b_emb, nullptr, nullptr, nullptr, nullptr,
                                                  hA, hA_hi, hA_lo, NN);
    }
    // [6] CSR fill
    fill_kernel<<<(EE + 255) / 256, 256>>>(src, dst, etype, cursor, edges);

    for (int l = 0; l < LL; ++l) {
        float* hin = l ? hB : hA;
        __nv_bfloat16* hin_hi = l ? hB_hi : hA_hi;
        __nv_bfloat16* hin_lo = l ? hB_lo : hA_lo;
        float* hout = l ? hA : hB;
        __nv_bfloat16* hout_hi = l ? hA_hi : hB_hi;
        __nv_bfloat16* hout_lo = l ? hA_lo : hB_lo;
        __nv_bfloat16* bch = Bc_hi + (size_t)l * DD * KCAT;
        __nv_bfloat16* bcl = Bc_lo + (size_t)l * DD * KCAT;

        gather_kernel<<<(NN * 32 + 255) / 256, 256>>>(rowptr, edges, hin, nodenorm,
                                                      w_coe, l, P_hi, P_lo);
        GemmChunks cl = {};
        cl.n = 10;
        for (int c = 0; c < 10; ++c) {
            if (c < 8) {
                cl.c[c].Ahi = P_hi + c * KCH; cl.c[c].Alo = P_lo + c * KCH; cl.c[c].lda = 512;
            } else {
                cl.c[c].Ahi = hin_hi + (c - 8) * KCH;
                cl.c[c].Alo = hin_lo + (c - 8) * KCH;
                cl.c[c].lda = DD;
            }
            cl.c[c].Bhi = bch + c * KCH;
            cl.c[c].Blo = bcl + c * KCH;
            cl.c[c].ldb = KCAT;
        }
        mma_gemm<<<ggrid, 256, SMEM_GEMM_TOTAL>>>(cl, nullptr,
                                                  bn_gamma + (size_t)l * DD,
                                                  bn_beta  + (size_t)l * DD,
                                                  bn_mean  + (size_t)l * DD,
                                                  bn_var   + (size_t)l * DD,
                                                  hout, hout_hi, hout_lo, NN);
    }

    cudaMemcpyAsync(d_out, hA, (size_t)NN * DD * sizeof(float), cudaMemcpyDeviceToDevice);
}

// round 6
// speedup vs baseline: 4.0022x; 1.2211x over previous
#include <cuda_runtime.h>
#include <cuda_fp16.h>
#include <cstdint>
#include <cstddef>

#define NN 50000
#define EE 800000
#define DD 128
#define RR 8
#define BB 4
#define LL 2
#define KCAT 640               // 4 bases * 128 + 128 self-loop
#define BN_EPS 1e-3f

#define KCH 64                 // k-chunk depth
#define RS 72                  // smem row stride (elements), 144B
#define TILE_E (128 * RS)      // 9216 elements per tile
#define STAGE_E (3 * TILE_E)   // A_hi, A_lo, B_hi
#define SMEM_GEMM_TOTAL (2 * STAGE_E * 2)   // 110592 bytes (2 stages)

// ---------------- device scratch ----------------
__device__ float   g_hA[(size_t)NN * DD];
__device__ float   g_hB[(size_t)NN * DD];
__device__ __half  g_hA_hi[(size_t)NN * DD];
__device__ __half  g_hA_lo[(size_t)NN * DD];
__device__ __half  g_hB_hi[(size_t)NN * DD];
__device__ __half  g_hB_lo[(size_t)NN * DD];
__device__ __half  g_nf_hi[(size_t)NN * DD];
__device__ __half  g_nf_lo[(size_t)NN * DD];
__device__ __half  g_P_hi[(size_t)NN * 512];
__device__ __half  g_P_lo[(size_t)NN * 512];
__device__ __half  g_Bc_h[2][(size_t)DD * KCAT];   // [n, k] ld=KCAT, per layer
__device__ __half  g_We_h[(size_t)DD * DD];
__device__ int     g_cnt[(size_t)RR * NN];
__device__ float   g_nodenorm[NN];
__device__ int     g_deg[NN];
__device__ int     g_rowptr[NN + 1];
__device__ int     g_cursor[NN];
__device__ int     g_bsum[256];
__device__ int     g_edges[EE];

// ================= helpers =================
__device__ __forceinline__ uint32_t smem_u32(const void* p) {
    uint32_t a;
    asm("{ .reg .u64 t; cvta.to.shared.u64 t, %1; cvt.u32.u64 %0, t; }" : "=r"(a) : "l"(p));
    return a;
}
__device__ __forceinline__ void ldm_x4(uint32_t* r, uint32_t addr) {
    asm volatile("ldmatrix.sync.aligned.m8n8.x4.shared.b16 {%0,%1,%2,%3}, [%4];"
                 : "=r"(r[0]), "=r"(r[1]), "=r"(r[2]), "=r"(r[3]) : "r"(addr));
}
__device__ __forceinline__ void mma16816(float* d, const uint32_t* a, const uint32_t* b) {
    asm volatile("mma.sync.aligned.m16n8k16.row.col.f32.f16.f16.f32 "
                 "{%0,%1,%2,%3}, {%4,%5,%6,%7}, {%8,%9}, {%0,%1,%2,%3};"
                 : "+f"(d[0]), "+f"(d[1]), "+f"(d[2]), "+f"(d[3])
                 : "r"(a[0]), "r"(a[1]), "r"(a[2]), "r"(a[3]), "r"(b[0]), "r"(b[1]));
}
__device__ __forceinline__ void cp_async16(uint32_t d, const void* s, int sz) {
    asm volatile("cp.async.cg.shared.global [%0], [%1], 16, %2;"
                 :: "r"(d), "l"(__cvta_generic_to_global(s)), "r"(sz));
}
// fp16 hi/lo split, packed pairs
__device__ __forceinline__ void split2h(float x0, float x1, uint32_t& hi, uint32_t& lo) {
    __half h0 = __float2half_rn(x0), h1 = __float2half_rn(x1);
    hi = (uint32_t)__half_as_ushort(h0) | ((uint32_t)__half_as_ushort(h1) << 16);
    __half l0 = __float2half_rn(x0 - __half2float(h0));
    __half l1 = __float2half_rn(x1 - __half2float(h1));
    lo = (uint32_t)__half_as_ushort(l0) | ((uint32_t)__half_as_ushort(l1) << 16);
}
__device__ __forceinline__ void split4h(float4 v, uint2& hi, uint2& lo) {
    split2h(v.x, v.y, hi.x, lo.x);
    split2h(v.z, v.w, hi.y, lo.y);
}

// ================= GEMM (HMMA fp16, 2-term split per k-chunk) ===========
// C[M,128] = sum_chunks (A_hi + A_lo)[:,64] @ (B_h[:,64])^T
struct Chunk { const __half *Ahi, *Alo, *Bh; int lda, ldb; };
struct GemmChunks { int n; Chunk c[10]; };

__global__ __launch_bounds__(256, 2)
void mma_gemm(GemmChunks ch,
              const float* __restrict__ bias,
              const float* __restrict__ bn_gamma, const float* __restrict__ bn_beta,
              const float* __restrict__ bn_mean, const float* __restrict__ bn_var,
              float* __restrict__ Cf, __half* __restrict__ Chi,
              __half* __restrict__ Clo, int M) {
    extern __shared__ __half smem[];
    const int tid = threadIdx.x;
    const int wid = tid >> 5;
    const int lane = tid & 31;
    const int warp_m = wid >> 2;
    const int warp_n = wid & 3;
    const int m0 = blockIdx.y * 128;

    auto load_chunk = [&](int c, int st) {
        const Chunk ck = ch.c[c];
        __half* s0 = smem + st * STAGE_E;
        #pragma unroll
        for (int i = 0; i < 4; ++i) {
            int t = tid + i * 256;          // 0..1023
            int row = t >> 3, kc = t & 7;   // kc: groups of 8 halves (16B)
            int gr = m0 + row;
            int ok = (gr < M);
            size_t ga = (size_t)(ok ? gr : 0);
            uint32_t so = smem_u32(s0 + row * RS + kc * 8);
            cp_async16(so,                ck.Ahi + ga * ck.lda + kc * 8, ok ? 16 : 0);
            cp_async16(so + TILE_E * 2,   ck.Alo + ga * ck.lda + kc * 8, ok ? 16 : 0);
            cp_async16(so + TILE_E * 4,   ck.Bh + (size_t)row * ck.ldb + kc * 8, 16);
        }
        asm volatile("cp.async.commit_group;" ::: "memory");
    };

    float acc[4][4][4];
    #pragma unroll
    for (int a = 0; a < 4; ++a)
        #pragma unroll
        for (int b = 0; b < 4; ++b)
            #pragma unroll
            for (int c = 0; c < 4; ++c) acc[a][b][c] = 0.f;

    const int a_row_off = (warp_m * 64 + (lane & 15)) * RS + ((lane >> 4) << 3);
    const int b_row_off = (warp_n * 32 + (lane & 7) + (((lane >> 4) & 1) << 3)) * RS
                          + (((lane >> 3) & 1) << 3);

    auto compute = [&](int st) {
        const uint32_t ub = smem_u32(smem + st * STAGE_E);
        const uint32_t uB = ub + (uint32_t)TILE_E * 4u;
        #pragma unroll
        for (int p = 0; p < 2; ++p) {             // (A_hi,B_h), (A_lo,B_h)
            const uint32_t uA = ub + (p ? (uint32_t)TILE_E * 2u : 0u);
            #pragma unroll
            for (int ks = 0; ks < 4; ++ks) {
                const int k0 = ks * 16;
                uint32_t afr[4][4];
                #pragma unroll
                for (int mt = 0; mt < 4; ++mt)
                    ldm_x4(afr[mt], uA + (uint32_t)(a_row_off + mt * 16 * RS + k0) * 2);
                uint32_t bfr[4][2];
                #pragma unroll
                for (int nt2 = 0; nt2 < 2; ++nt2) {
                    uint32_t r[4];
                    ldm_x4(r, uB + (uint32_t)(b_row_off + nt2 * 16 * RS + k0) * 2);
                    bfr[nt2 * 2 + 0][0] = r[0]; bfr[nt2 * 2 + 0][1] = r[1];
                    bfr[nt2 * 2 + 1][0] = r[2]; bfr[nt2 * 2 + 1][1] = r[3];
                }
                #pragma unroll
                for (int mt = 0; mt < 4; ++mt)
                    #pragma unroll
                    for (int nt = 0; nt < 4; ++nt)
                        mma16816(acc[mt][nt], afr[mt], bfr[nt]);
            }
        }
    };

    const int NC = ch.n;
    load_chunk(0, 0);
    for (int c = 0; c < NC; ++c) {
        if (c + 1 < NC) {
            load_chunk(c + 1, (c + 1) & 1);
            asm volatile("cp.async.wait_group 1;" ::: "memory");
        } else {
            asm volatile("cp.async.wait_group 0;" ::: "memory");
        }
        __syncthreads();
        compute(c & 1);
        __syncthreads();
    }

    // ---- epilogue: bias / BN+ReLU, fp32 out + fused fp16 hi/lo split ----
    const bool has_bn = (bn_gamma != nullptr);
    const int mrow = m0 + warp_m * 64 + (lane >> 2);
    const int ncol = warp_n * 32 + 2 * (lane & 3);
    #pragma unroll
    for (int mt = 0; mt < 4; ++mt) {
        #pragma unroll
        for (int half = 0; half < 2; ++half) {
            int gr = mrow + mt * 16 + half * 8;
            if (gr >= M) continue;
            #pragma unroll
            for (int nt = 0; nt < 4; ++nt) {
                int col = ncol + nt * 8;
                float x0 = acc[mt][nt][half * 2 + 0];
                float x1 = acc[mt][nt][half * 2 + 1];
                if (bias) { x0 += __ldg(bias + col); x1 += __ldg(bias + col + 1); }
                if (has_bn) {
                    float g0 = __ldg(bn_gamma + col), g1 = __ldg(bn_gamma + col + 1);
                    float be0 = __ldg(bn_beta + col), be1 = __ldg(bn_beta + col + 1);
                    float mn0 = __ldg(bn_mean + col), mn1 = __ldg(bn_mean + col + 1);
                    float vr0 = __ldg(bn_var + col), vr1 = __ldg(bn_var + col + 1);
                    x0 = fmaxf(g0 * (x0 - mn0) * rsqrtf(vr0 + BN_EPS) + be0, 0.f);
                    x1 = fmaxf(g1 * (x1 - mn1) * rsqrtf(vr1 + BN_EPS) + be1, 0.f);
                }
                float2 o; o.x = x0; o.y = x1;
                *(float2*)(Cf + (size_t)gr * DD + col) = o;
                uint32_t ph, pl;
                split2h(x0, x1, ph, pl);
                *(uint32_t*)(Chi + (size_t)gr * DD + col) = ph;
                *(uint32_t*)(Clo + (size_t)gr * DD + col) = pl;
            }
        }
    }
}

// ================= fused prep (block-range dispatch) =================
#define PB_SPLIT 6250                  // NN*32/256
#define PB_COUNT (PB_SPLIT + 3125)     // EE/256
#define PB_WEMB  (PB_COUNT + 64)       // DD*DD/256
#define PB_BC0   (PB_WEMB + 320)       // DD*KCAT/256
#define PB_BC1   (PB_BC0 + 320)

__global__ __launch_bounds__(256)
void prep_kernel(const float* __restrict__ node_feat, const float* __restrict__ W_emb,
                 const float* __restrict__ bases, const float* __restrict__ self_loop,
                 const int* __restrict__ dst, const int* __restrict__ etype,
                 int* __restrict__ cnt,
                 __half* __restrict__ nf_hi, __half* __restrict__ nf_lo,
                 __half* __restrict__ We_h,
                 __half* __restrict__ Bc0_h, __half* __restrict__ Bc1_h) {
    int b = blockIdx.x;
    int t = threadIdx.x;
    if (b < PB_SPLIT) {
        int i = b * 256 + t;
        float4 v = ((const float4*)node_feat)[i];
        uint2 ph, pl;
        split4h(v, ph, pl);
        ((uint2*)nf_hi)[i] = ph;
        ((uint2*)nf_lo)[i] = pl;
    } else if (b < PB_COUNT) {
        int e = (b - PB_SPLIT) * 256 + t;
        if (e < EE) atomicAdd(&cnt[(size_t)etype[e] * NN + dst[e]], 1);
    } else if (b < PB_WEMB) {
        int i = (b - PB_COUNT) * 256 + t;        // over DD*DD
        int n = i >> 7, k = i & 127;
        We_h[i] = __float2half_rn(W_emb[(size_t)k * DD + n]);
    } else {
        int l = (b < PB_BC0) ? 0 : 1;
        int i = (b - (l ? PB_BC0 : PB_WEMB)) * 256 + t;   // over DD*KCAT
        int n = i / KCAT, k = i - n * KCAT;
        float v;
        if (k < 512) {
            int bb = k >> 7, d = k & 127;
            v = bases[(size_t)l * BB * DD * DD + (size_t)bb * DD * DD + (size_t)d * DD + n];
        } else {
            v = self_loop[(size_t)l * DD * DD + (size_t)(k - 512) * DD + n];
        }
        __half h = __float2half_rn(v);
        if (l == 0) Bc0_h[i] = h;
        else        Bc1_h[i] = h;
    }
}

// norm + deg + per-block deg sum
__global__ __launch_bounds__(256) void normd_kernel(const int* __restrict__ cnt,
                                                    float* __restrict__ nodenorm,
                                                    int* __restrict__ deg,
                                                    int* __restrict__ bsum) {
    __shared__ int s[256];
    int n = blockIdx.x * 256 + threadIdx.x;
    int d = 0;
    if (n < NN) {
        float v = 0.f;
        bool found = false;
        #pragma unroll
        for (int r = RR - 1; r >= 0; --r) {
            int c = cnt[(size_t)r * NN + n];
            d += c;
            if (!found && c > 0) { v = 1.0f / (float)c; found = true; }
        }
        nodenorm[n] = v;
        deg[n] = d;
    }
    s[threadIdx.x] = d;
    __syncthreads();
    for (int o = 128; o > 0; o >>= 1) {
        if (threadIdx.x < o) s[threadIdx.x] += s[threadIdx.x + o];
        __syncthreads();
    }
    if (threadIdx.x == 0) bsum[blockIdx.x] = s[0];
}

// rowptr/cursor; block offset computed in-block from raw bsum (nb <= 256)
__global__ void scan3(const int* __restrict__ deg, const int* __restrict__ bsum,
                      int* __restrict__ rowptr, int* __restrict__ cursor) {
    __shared__ int s[256];
    __shared__ int soff;
    int t = threadIdx.x;
    // exclusive offset = sum of bsum[j] for j < blockIdx.x
    s[t] = (t < blockIdx.x) ? bsum[t] : 0;
    __syncthreads();
    for (int o = 128; o > 0; o >>= 1) {
        if (t < o) s[t] += s[t + o];
        __syncthreads();
    }
    if (t == 0) soff = s[0];
    __syncthreads();

    int i = blockIdx.x * 256 + t;
    int v = (i < NN) ? deg[i] : 0;
    s[t] = v;
    __syncthreads();
    for (int o = 1; o < 256; o <<= 1) {
        int u = (t >= o) ? s[t - o] : 0;
        __syncthreads();
        s[t] += u;
        __syncthreads();
    }
    int incl = s[t];
    if (i < NN) {
        rowptr[i] = soff + incl - v;
        cursor[i] = soff + incl - v;
        if (i == NN - 1) rowptr[NN] = soff + incl;
    }
}

__global__ __launch_bounds__(256) void fill_kernel(const int* __restrict__ src,
                                                   const int* __restrict__ dst,
                                                   const int* __restrict__ etype,
                                                   int* __restrict__ cursor,
                                                   int* __restrict__ edges) {
    int e = blockIdx.x * blockDim.x + threadIdx.x;
    if (e >= EE) return;
    int p = atomicAdd(&cursor[dst[e]], 1);
    edges[p] = src[e] | (etype[e] << 16);
}

// ================= gather: P_b[dst] = norm[dst] * sum_in w_coe[r,b] * h[src] =========
__global__ __launch_bounds__(256) void gather_kernel(const int* __restrict__ rowptr,
                                                     const int* __restrict__ edges,
                                                     const float* __restrict__ h,
                                                     const float* __restrict__ nodenorm,
                                                     const float* __restrict__ w_coe, int l,
                                                     __half* __restrict__ Phi,
                                                     __half* __restrict__ Plo) {
    __shared__ float swc[RR * BB];
    if (threadIdx.x < RR * BB) swc[threadIdx.x] = w_coe[l * RR * BB + threadIdx.x];
    __syncthreads();

    int gw = (blockIdx.x * 256 + threadIdx.x) >> 5;
    int lane = threadIdx.x & 31;
    if (gw >= NN) return;

    float4 a0 = make_float4(0.f, 0.f, 0.f, 0.f), a1 = a0, a2 = a0, a3 = a0;
    const int beg = rowptr[gw], end = rowptr[gw + 1];

    auto accum = [&](int ev, float4 v) {
        int r = ev >> 16;
        float w0 = swc[r * 4 + 0], w1 = swc[r * 4 + 1];
        float w2 = swc[r * 4 + 2], w3 = swc[r * 4 + 3];
        a0.x += w0 * v.x; a0.y += w0 * v.y; a0.z += w0 * v.z; a0.w += w0 * v.w;
        a1.x += w1 * v.x; a1.y += w1 * v.y; a1.z += w1 * v.z; a1.w += w1 * v.w;
        a2.x += w2 * v.x; a2.y += w2 * v.y; a2.z += w2 * v.z; a2.w += w2 * v.w;
        a3.x += w3 * v.x; a3.y += w3 * v.y; a3.z += w3 * v.z; a3.w += w3 * v.w;
    };

    int i = beg;
    for (; i + 4 <= end; i += 4) {
        int e0 = edges[i], e1 = edges[i + 1], e2 = edges[i + 2], e3 = edges[i + 3];
        float4 v0 = *(const float4*)(h + (size_t)(e0 & 0xFFFF) * DD + lane * 4);
        float4 v1 = *(const float4*)(h + (size_t)(e1 & 0xFFFF) * DD + lane * 4);
        float4 v2 = *(const float4*)(h + (size_t)(e2 & 0xFFFF) * DD + lane * 4);
        float4 v3 = *(const float4*)(h + (size_t)(e3 & 0xFFFF) * DD + lane * 4);
        accum(e0, v0); accum(e1, v1); accum(e2, v2); accum(e3, v3);
    }
    for (; i < end; ++i) {
        int ev = edges[i];
        float4 v = *(const float4*)(h + (size_t)(ev & 0xFFFF) * DD + lane * 4);
        accum(ev, v);
    }

    float nrm = nodenorm[gw];
    a0.x *= nrm; a0.y *= nrm; a0.z *= nrm; a0.w *= nrm;
    a1.x *= nrm; a1.y *= nrm; a1.z *= nrm; a1.w *= nrm;
    a2.x *= nrm; a2.y *= nrm; a2.z *= nrm; a2.w *= nrm;
    a3.x *= nrm; a3.y *= nrm; a3.z *= nrm; a3.w *= nrm;

    uint2 ph, pl;
    size_t base = (size_t)gw * 512 + lane * 4;
    split4h(a0, ph, pl);
    *(uint2*)(Phi + base) = ph;           *(uint2*)(Plo + base) = pl;
    split4h(a1, ph, pl);
    *(uint2*)(Phi + base + 128) = ph;     *(uint2*)(Plo + base + 128) = pl;
    split4h(a2, ph, pl);
    *(uint2*)(Phi + base + 256) = ph;     *(uint2*)(Plo + base + 256) = pl;
    split4h(a3, ph, pl);
    *(uint2*)(Phi + base + 384) = ph;     *(uint2*)(Plo + base + 384) = pl;
}

// ================= launcher =================
extern "C" void kernel_launch(void* const* d_in, const int* in_sizes, int n_in,
                              void* d_out, int out_size) {
    const float* node_feat = (const float*)d_in[0];
    const float* W_emb     = (const float*)d_in[1];
    const float* b_emb     = (const float*)d_in[2];
    const float* bases     = (const float*)d_in[3];
    const float* w_coe     = (const float*)d_in[4];
    const float* self_loop = (const float*)d_in[5];
    const float* bn_gamma  = (const float*)d_in[6];
    const float* bn_beta   = (const float*)d_in[7];
    const float* bn_mean   = (const float*)d_in[8];
    const float* bn_var    = (const float*)d_in[9];
    const int*   src       = (const int*)d_in[10];
    const int*   dst       = (const int*)d_in[11];
    const int*   etype     = (const int*)d_in[12];

    float *hA, *hB, *nodenorm;
    __half *hA_hi, *hA_lo, *hB_hi, *hB_lo, *nf_hi, *nf_lo;
    __half *P_hi, *P_lo, *Bc_h, *We_h;
    int *cnt, *deg, *rowptr, *cursor, *bsum, *edges;
    cudaGetSymbolAddress((void**)&hA, g_hA);
    cudaGetSymbolAddress((void**)&hB, g_hB);
    cudaGetSymbolAddress((void**)&hA_hi, g_hA_hi);
    cudaGetSymbolAddress((void**)&hA_lo, g_hA_lo);
    cudaGetSymbolAddress((void**)&hB_hi, g_hB_hi);
    cudaGetSymbolAddress((void**)&hB_lo, g_hB_lo);
    cudaGetSymbolAddress((void**)&nf_hi, g_nf_hi);
    cudaGetSymbolAddress((void**)&nf_lo, g_nf_lo);
    cudaGetSymbolAddress((void**)&P_hi, g_P_hi);
    cudaGetSymbolAddress((void**)&P_lo, g_P_lo);
    cudaGetSymbolAddress((void**)&Bc_h, g_Bc_h);
    cudaGetSymbolAddress((void**)&We_h, g_We_h);
    cudaGetSymbolAddress((void**)&cnt, g_cnt);
    cudaGetSymbolAddress((void**)&nodenorm, g_nodenorm);
    cudaGetSymbolAddress((void**)&deg, g_deg);
    cudaGetSymbolAddress((void**)&rowptr, g_rowptr);
    cudaGetSymbolAddress((void**)&cursor, g_cursor);
    cudaGetSymbolAddress((void**)&bsum, g_bsum);
    cudaGetSymbolAddress((void**)&edges, g_edges);

    cudaFuncSetAttribute(mma_gemm, cudaFuncAttributeMaxDynamicSharedMemorySize, SMEM_GEMM_TOTAL);

    const int NB = (NN + 255) / 256;   // 196
    dim3 ggrid(1, (NN + 127) / 128);

    // [0] zero counts (driver memset node)
    cudaMemsetAsync(cnt, 0, (size_t)RR * NN * sizeof(int));
    // [1] fused prep: split(nf fp16) + count + WembT fp16 + Bcat fp16 (l=0,1)
    prep_kernel<<<PB_BC1, 256>>>(node_feat, W_emb, bases, self_loop, dst, etype, cnt,
                                 nf_hi, nf_lo, We_h,
                                 &Bc_h[0], &Bc_h[(size_t)DD * KCAT]);
    // [2] embedding GEMM: hA = nf @ W_emb + b_emb
    {
        GemmChunks ce = {};
        ce.n = 2;
        for (int c = 0; c < 2; ++c) {
            ce.c[c].Ahi = nf_hi + c * KCH; ce.c[c].Alo = nf_lo + c * KCH; ce.c[c].lda = DD;
            ce.c[c].Bh  = We_h + c * KCH;  ce.c[c].ldb = DD;
        }
        mma_gemm<<<ggrid, 256, SMEM_GEMM_TOTAL>>>(ce, b_emb, nullptr, nullptr, nullptr, nullptr,
                                                  hA, hA_hi, hA_lo, NN);
    }
    // [3] norm + deg + block sums
    normd_kernel<<<NB, 256>>>(cnt, nodenorm, deg, bsum);
    // [4] rowptr/cursor (offset computed in-block)
    scan3<<<NB, 256>>>(deg, bsum, rowptr, cursor);
    // [5] CSR fill
    fill_kernel<<<(EE + 255) / 256, 256>>>(src, dst, etype, cursor, edges);

    for (int l = 0; l < LL; ++l) {
        float* hin = l ? hB : hA;
        __half* hin_hi = l ? hB_hi : hA_hi;
        __half* hin_lo = l ? hB_lo : hA_lo;
        float* hout = l ? hA : hB;
        __half* hout_hi = l ? hA_hi : hB_hi;
        __half* hout_lo = l ? hA_lo : hB_lo;
        __half* bch = Bc_h + (size_t)l * DD * KCAT;

        gather_kernel<<<(NN * 32 + 255) / 256, 256>>>(rowptr, edges, hin, nodenorm,
                                                      w_coe, l, P_hi, P_lo);
        GemmChunks cl = {};
        cl.n = 10;
        for (int c = 0; c < 10; ++c) {
            if (c < 8) {
                cl.c[c].Ahi = P_hi + c * KCH; cl.c[c].Alo = P_lo + c * KCH; cl.c[c].lda = 512;
            } else {
                cl.c[c].Ahi = hin_hi + (c - 8) * KCH;
                cl.c[c].Alo = hin_lo + (c - 8) * KCH;
                cl.c[c].lda = DD;
            }
            cl.c[c].Bh  = bch + c * KCH;
            cl.c[c].ldb = KCAT;
        }
        mma_gemm<<<ggrid, 256, SMEM_GEMM_TOTAL>>>(cl, nullptr,
                                                  bn_gamma + (size_t)l * DD,
                                                  bn_beta  + (size_t)l * DD,
                                                  bn_mean  + (size_t)l * DD,
                                                  bn_var   + (size_t)l * DD,
                                                  hout, hout_hi, hout_lo, NN);
    }

    cudaMemcpyAsync(d_out, hA, (size_t)NN * DD * sizeof(float), cudaMemcpyDeviceToDevice);
}

// round 7
// speedup vs baseline: 4.2455x; 1.0608x over previous
#include <cuda_runtime.h>
#include <cuda_fp16.h>
#include <cstdint>
#include <cstddef>

#define NN 50000
#define EE 800000
#define DD 128
#define RR 8
#define BB 4
#define LL 2
#define KCAT 640               // 4 bases * 128 + 128 self-loop
#define BN_EPS 1e-3f

#define KCH 64                 // k-chunk depth
#define RS 72                  // smem row stride (elements), 144B
#define TILE_A_E (64 * RS)     // 4608 elements (64-row A tile)
#define TILE_B_E (128 * RS)    // 9216 elements (128-row B tile)
#define STAGE_E (2 * TILE_A_E + TILE_B_E)   // A_hi, A_lo, B  = 18432 elem
#define SMEM_GEMM_TOTAL (2 * STAGE_E * 2)   // 73728 bytes (2 stages)

// ---------------- device scratch ----------------
__device__ __half  g_hA_hi[(size_t)NN * DD];
__device__ __half  g_hA_lo[(size_t)NN * DD];
__device__ __half  g_hB_hi[(size_t)NN * DD];
__device__ __half  g_hB_lo[(size_t)NN * DD];
__device__ __half  g_nf_hi[(size_t)NN * DD];
__device__ __half  g_nf_lo[(size_t)NN * DD];
__device__ __half  g_P_hi[(size_t)NN * 512];
__device__ __half  g_P_lo[(size_t)NN * 512];
__device__ __half  g_Bc_h[2][(size_t)DD * KCAT];   // [n, k] ld=KCAT, per layer
__device__ __half  g_We_h[(size_t)DD * DD];
__device__ int     g_cnt[(size_t)RR * NN];
__device__ float   g_nodenorm[NN];
__device__ int     g_deg[NN];
__device__ int     g_rowptr[NN + 1];
__device__ int     g_cursor[NN];
__device__ int     g_bsum[256];
__device__ int     g_edges[EE];

// ================= helpers =================
__device__ __forceinline__ uint32_t smem_u32(const void* p) {
    uint32_t a;
    asm("{ .reg .u64 t; cvta.to.shared.u64 t, %1; cvt.u32.u64 %0, t; }" : "=r"(a) : "l"(p));
    return a;
}
__device__ __forceinline__ void ldm_x4(uint32_t* r, uint32_t addr) {
    asm volatile("ldmatrix.sync.aligned.m8n8.x4.shared.b16 {%0,%1,%2,%3}, [%4];"
                 : "=r"(r[0]), "=r"(r[1]), "=r"(r[2]), "=r"(r[3]) : "r"(addr));
}
__device__ __forceinline__ void mma16816(float* d, const uint32_t* a, const uint32_t* b) {
    asm volatile("mma.sync.aligned.m16n8k16.row.col.f32.f16.f16.f32 "
                 "{%0,%1,%2,%3}, {%4,%5,%6,%7}, {%8,%9}, {%0,%1,%2,%3};"
                 : "+f"(d[0]), "+f"(d[1]), "+f"(d[2]), "+f"(d[3])
                 : "r"(a[0]), "r"(a[1]), "r"(a[2]), "r"(a[3]), "r"(b[0]), "r"(b[1]));
}
__device__ __forceinline__ void cp_async16(uint32_t d, const void* s, int sz) {
    asm volatile("cp.async.cg.shared.global [%0], [%1], 16, %2;"
                 :: "r"(d), "l"(__cvta_generic_to_global(s)), "r"(sz));
}
__device__ __forceinline__ void split2h(float x0, float x1, uint32_t& hi, uint32_t& lo) {
    __half h0 = __float2half_rn(x0), h1 = __float2half_rn(x1);
    hi = (uint32_t)__half_as_ushort(h0) | ((uint32_t)__half_as_ushort(h1) << 16);
    __half l0 = __float2half_rn(x0 - __half2float(h0));
    __half l1 = __float2half_rn(x1 - __half2float(h1));
    lo = (uint32_t)__half_as_ushort(l0) | ((uint32_t)__half_as_ushort(l1) << 16);
}
__device__ __forceinline__ void split4h(float4 v, uint2& hi, uint2& lo) {
    split2h(v.x, v.y, hi.x, lo.x);
    split2h(v.z, v.w, hi.y, lo.y);
}

// ================= GEMM (HMMA fp16, 2-term split, 64x128 tiles, 3 CTA/SM) =========
// C[M,128] = sum_chunks (A_hi + A_lo)[:,64] @ (B_h[:,64])^T
struct Chunk { const __half *Ahi, *Alo, *Bh; int lda, ldb; };
struct GemmChunks { int n; Chunk c[10]; };

__global__ __launch_bounds__(256, 3)
void mma_gemm(GemmChunks ch,
              const float* __restrict__ bias,
              const float* __restrict__ bn_gamma, const float* __restrict__ bn_beta,
              const float* __restrict__ bn_mean, const float* __restrict__ bn_var,
              float* __restrict__ Cf, __half* __restrict__ Chi,
              __half* __restrict__ Clo, int M) {
    extern __shared__ __half smem[];
    const int tid = threadIdx.x;
    const int wid = tid >> 5;
    const int lane = tid & 31;
    const int warp_m = wid >> 2;          // 0..1, 32 rows each
    const int warp_n = wid & 3;           // 0..3, 32 cols each
    const int m0 = blockIdx.y * 64;

    auto load_chunk = [&](int c, int st) {
        const Chunk ck = ch.c[c];
        __half* s0 = smem + st * STAGE_E;
        // A_hi + A_lo: 64 rows x 8 (16B groups) = 512 slots each
        #pragma unroll
        for (int i = 0; i < 2; ++i) {
            int t = tid + i * 256;          // 0..511
            int row = t >> 3, kc = t & 7;
            int gr = m0 + row;
            int ok = (gr < M);
            size_t ga = (size_t)(ok ? gr : 0);
            uint32_t so = smem_u32(s0 + row * RS + kc * 8);
            cp_async16(so,                  ck.Ahi + ga * ck.lda + kc * 8, ok ? 16 : 0);
            cp_async16(so + TILE_A_E * 2,   ck.Alo + ga * ck.lda + kc * 8, ok ? 16 : 0);
        }
        // B: 128 rows x 8 = 1024 slots
        #pragma unroll
        for (int i = 0; i < 4; ++i) {
            int t = tid + i * 256;
            int row = t >> 3, kc = t & 7;
            cp_async16(smem_u32(s0 + 2 * TILE_A_E + row * RS + kc * 8),
                       ck.Bh + (size_t)row * ck.ldb + kc * 8, 16);
        }
        asm volatile("cp.async.commit_group;" ::: "memory");
    };

    float acc[2][4][4];
    #pragma unroll
    for (int a = 0; a < 2; ++a)
        #pragma unroll
        for (int b = 0; b < 4; ++b)
            #pragma unroll
            for (int c = 0; c < 4; ++c) acc[a][b][c] = 0.f;

    const int a_row_off = (warp_m * 32 + (lane & 15)) * RS + ((lane >> 4) << 3);
    const int b_row_off = (warp_n * 32 + (lane & 7) + (((lane >> 4) & 1) << 3)) * RS
                          + (((lane >> 3) & 1) << 3);

    auto compute = [&](int st) {
        const uint32_t ub = smem_u32(smem + st * STAGE_E);
        const uint32_t uAhi = ub;
        const uint32_t uAlo = ub + (uint32_t)TILE_A_E * 2u;
        const uint32_t uB   = ub + (uint32_t)TILE_A_E * 4u;
        #pragma unroll
        for (int ks = 0; ks < 4; ++ks) {
            const int k0 = ks * 16;
            // B fragments once, reused for both A terms
            uint32_t bfr[4][2];
            #pragma unroll
            for (int nt2 = 0; nt2 < 2; ++nt2) {
                uint32_t r[4];
                ldm_x4(r, uB + (uint32_t)(b_row_off + nt2 * 16 * RS + k0) * 2);
                bfr[nt2 * 2 + 0][0] = r[0]; bfr[nt2 * 2 + 0][1] = r[1];
                bfr[nt2 * 2 + 1][0] = r[2]; bfr[nt2 * 2 + 1][1] = r[3];
            }
            uint32_t afr[2][4];
            #pragma unroll
            for (int mt = 0; mt < 2; ++mt)
                ldm_x4(afr[mt], uAhi + (uint32_t)(a_row_off + mt * 16 * RS + k0) * 2);
            #pragma unroll
            for (int mt = 0; mt < 2; ++mt)
                #pragma unroll
                for (int nt = 0; nt < 4; ++nt)
                    mma16816(acc[mt][nt], afr[mt], bfr[nt]);
            #pragma unroll
            for (int mt = 0; mt < 2; ++mt)
                ldm_x4(afr[mt], uAlo + (uint32_t)(a_row_off + mt * 16 * RS + k0) * 2);
            #pragma unroll
            for (int mt = 0; mt < 2; ++mt)
                #pragma unroll
                for (int nt = 0; nt < 4; ++nt)
                    mma16816(acc[mt][nt], afr[mt], bfr[nt]);
        }
    };

    const int NC = ch.n;
    load_chunk(0, 0);
    for (int c = 0; c < NC; ++c) {
        if (c + 1 < NC) {
            load_chunk(c + 1, (c + 1) & 1);
            asm volatile("cp.async.wait_group 1;" ::: "memory");
        } else {
            asm volatile("cp.async.wait_group 0;" ::: "memory");
        }
        __syncthreads();
        compute(c & 1);
        __syncthreads();
    }

    // ---- epilogue: bias / BN+ReLU; optional fp32 out; optional fp16 hi/lo split ----
    const bool has_bn = (bn_gamma != nullptr);
    const int mrow = m0 + warp_m * 32 + (lane >> 2);
    const int ncol = warp_n * 32 + 2 * (lane & 3);
    #pragma unroll
    for (int mt = 0; mt < 2; ++mt) {
        #pragma unroll
        for (int half = 0; half < 2; ++half) {
            int gr = mrow + mt * 16 + half * 8;
            if (gr >= M) continue;
            #pragma unroll
            for (int nt = 0; nt < 4; ++nt) {
                int col = ncol + nt * 8;
                float x0 = acc[mt][nt][half * 2 + 0];
                float x1 = acc[mt][nt][half * 2 + 1];
                if (bias) { x0 += __ldg(bias + col); x1 += __ldg(bias + col + 1); }
                if (has_bn) {
                    float g0 = __ldg(bn_gamma + col), g1 = __ldg(bn_gamma + col + 1);
                    float be0 = __ldg(bn_beta + col), be1 = __ldg(bn_beta + col + 1);
                    float mn0 = __ldg(bn_mean + col), mn1 = __ldg(bn_mean + col + 1);
                    float vr0 = __ldg(bn_var + col), vr1 = __ldg(bn_var + col + 1);
                    x0 = fmaxf(g0 * (x0 - mn0) * rsqrtf(vr0 + BN_EPS) + be0, 0.f);
                    x1 = fmaxf(g1 * (x1 - mn1) * rsqrtf(vr1 + BN_EPS) + be1, 0.f);
                }
                if (Cf) {
                    float2 o; o.x = x0; o.y = x1;
                    *(float2*)(Cf + (size_t)gr * DD + col) = o;
                }
                if (Chi) {
                    uint32_t ph, pl;
                    split2h(x0, x1, ph, pl);
                    *(uint32_t*)(Chi + (size_t)gr * DD + col) = ph;
                    *(uint32_t*)(Clo + (size_t)gr * DD + col) = pl;
                }
            }
        }
    }
}

// ================= fused prep (block-range dispatch) =================
#define PB_SPLIT 6250                  // NN*32/256
#define PB_COUNT (PB_SPLIT + 3125)     // EE/256
#define PB_WEMB  (PB_COUNT + 64)       // DD*DD/256
#define PB_BC0   (PB_WEMB + 320)       // DD*KCAT/256
#define PB_BC1   (PB_BC0 + 320)

__global__ __launch_bounds__(256)
void prep_kernel(const float* __restrict__ node_feat, const float* __restrict__ W_emb,
                 const float* __restrict__ bases, const float* __restrict__ self_loop,
                 const int* __restrict__ dst, const int* __restrict__ etype,
                 int* __restrict__ cnt,
                 __half* __restrict__ nf_hi, __half* __restrict__ nf_lo,
                 __half* __restrict__ We_h,
                 __half* __restrict__ Bc0_h, __half* __restrict__ Bc1_h) {
    int b = blockIdx.x;
    int t = threadIdx.x;
    if (b < PB_SPLIT) {
        int i = b * 256 + t;
        float4 v = ((const float4*)node_feat)[i];
        uint2 ph, pl;
        split4h(v, ph, pl);
        ((uint2*)nf_hi)[i] = ph;
        ((uint2*)nf_lo)[i] = pl;
    } else if (b < PB_COUNT) {
        int e = (b - PB_SPLIT) * 256 + t;
        if (e < EE) atomicAdd(&cnt[(size_t)etype[e] * NN + dst[e]], 1);
    } else if (b < PB_WEMB) {
        int i = (b - PB_COUNT) * 256 + t;        // over DD*DD
        int n = i >> 7, k = i & 127;
        We_h[i] = __float2half_rn(W_emb[(size_t)k * DD + n]);
    } else {
        int l = (b < PB_BC0) ? 0 : 1;
        int i = (b - (l ? PB_BC0 : PB_WEMB)) * 256 + t;   // over DD*KCAT
        int n = i / KCAT, k = i - n * KCAT;
        float v;
        if (k < 512) {
            int bb = k >> 7, d = k & 127;
            v = bases[(size_t)l * BB * DD * DD + (size_t)bb * DD * DD + (size_t)d * DD + n];
        } else {
            v = self_loop[(size_t)l * DD * DD + (size_t)(k - 512) * DD + n];
        }
        __half h = __float2half_rn(v);
        if (l == 0) Bc0_h[i] = h;
        else        Bc1_h[i] = h;
    }
}

// norm + deg + per-block deg sum
__global__ __launch_bounds__(256) void normd_kernel(const int* __restrict__ cnt,
                                                    float* __restrict__ nodenorm,
                                                    int* __restrict__ deg,
                                                    int* __restrict__ bsum) {
    __shared__ int s[256];
    int n = blockIdx.x * 256 + threadIdx.x;
    int d = 0;
    if (n < NN) {
        float v = 0.f;
        bool found = false;
        #pragma unroll
        for (int r = RR - 1; r >= 0; --r) {
            int c = cnt[(size_t)r * NN + n];
            d += c;
            if (!found && c > 0) { v = 1.0f / (float)c; found = true; }
        }
        nodenorm[n] = v;
        deg[n] = d;
    }
    s[threadIdx.x] = d;
    __syncthreads();
    for (int o = 128; o > 0; o >>= 1) {
        if (threadIdx.x < o) s[threadIdx.x] += s[threadIdx.x + o];
        __syncthreads();
    }
    if (threadIdx.x == 0) bsum[blockIdx.x] = s[0];
}

// rowptr/cursor; block offset computed in-block from raw bsum (nb <= 256)
__global__ void scan3(const int* __restrict__ deg, const int* __restrict__ bsum,
                      int* __restrict__ rowptr, int* __restrict__ cursor) {
    __shared__ int s[256];
    __shared__ int soff;
    int t = threadIdx.x;
    s[t] = (t < blockIdx.x) ? bsum[t] : 0;
    __syncthreads();
    for (int o = 128; o > 0; o >>= 1) {
        if (t < o) s[t] += s[t + o];
        __syncthreads();
    }
    if (t == 0) soff = s[0];
    __syncthreads();

    int i = blockIdx.x * 256 + t;
    int v = (i < NN) ? deg[i] : 0;
    s[t] = v;
    __syncthreads();
    for (int o = 1; o < 256; o <<= 1) {
        int u = (t >= o) ? s[t - o] : 0;
        __syncthreads();
        s[t] += u;
        __syncthreads();
    }
    int incl = s[t];
    if (i < NN) {
        rowptr[i] = soff + incl - v;
        cursor[i] = soff + incl - v;
        if (i == NN - 1) rowptr[NN] = soff + incl;
    }
}

__global__ __launch_bounds__(256) void fill_kernel(const int* __restrict__ src,
                                                   const int* __restrict__ dst,
                                                   const int* __restrict__ etype,
                                                   int* __restrict__ cursor,
                                                   int* __restrict__ edges) {
    int e = blockIdx.x * blockDim.x + threadIdx.x;
    if (e >= EE) return;
    int p = atomicAdd(&cursor[dst[e]], 1);
    edges[p] = src[e] | (etype[e] << 16);
}

// ================= gather: P_b[dst] = norm[dst] * sum_in w_coe[r,b] * h[src] =========
// h reconstructed from fp16 hi+lo (error ~2^-22, negligible)
__global__ __launch_bounds__(256) void gather_kernel(const int* __restrict__ rowptr,
                                                     const int* __restrict__ edges,
                                                     const __half* __restrict__ hhi,
                                                     const __half* __restrict__ hlo,
                                                     const float* __restrict__ nodenorm,
                                                     const float* __restrict__ w_coe, int l,
                                                     __half* __restrict__ Phi,
                                                     __half* __restrict__ Plo) {
    __shared__ float swc[RR * BB];
    if (threadIdx.x < RR * BB) swc[threadIdx.x] = w_coe[l * RR * BB + threadIdx.x];
    __syncthreads();

    int gw = (blockIdx.x * 256 + threadIdx.x) >> 5;
    int lane = threadIdx.x & 31;
    if (gw >= NN) return;

    float4 a0 = make_float4(0.f, 0.f, 0.f, 0.f), a1 = a0, a2 = a0, a3 = a0;
    const int beg = rowptr[gw], end = rowptr[gw + 1];

    auto fetch = [&](int s) -> float4 {
        uint2 uh = *(const uint2*)(hhi + (size_t)s * DD + lane * 4);
        uint2 ul = *(const uint2*)(hlo + (size_t)s * DD + lane * 4);
        __half2 h0 = *(__half2*)&uh.x, h1 = *(__half2*)&uh.y;
        __half2 l0 = *(__half2*)&ul.x, l1 = *(__half2*)&ul.y;
        float2 f0 = __half22float2(h0), f1 = __half22float2(h1);
        float2 g0 = __half22float2(l0), g1 = __half22float2(l1);
        return make_float4(f0.x + g0.x, f0.y + g0.y, f1.x + g1.x, f1.y + g1.y);
    };
    auto accum = [&](int ev, float4 v) {
        int r = ev >> 16;
        float w0 = swc[r * 4 + 0], w1 = swc[r * 4 + 1];
        float w2 = swc[r * 4 + 2], w3 = swc[r * 4 + 3];
        a0.x += w0 * v.x; a0.y += w0 * v.y; a0.z += w0 * v.z; a0.w += w0 * v.w;
        a1.x += w1 * v.x; a1.y += w1 * v.y; a1.z += w1 * v.z; a1.w += w1 * v.w;
        a2.x += w2 * v.x; a2.y += w2 * v.y; a2.z += w2 * v.z; a2.w += w2 * v.w;
        a3.x += w3 * v.x; a3.y += w3 * v.y; a3.z += w3 * v.z; a3.w += w3 * v.w;
    };

    int i = beg;
    for (; i + 4 <= end; i += 4) {
        int e0 = edges[i], e1 = edges[i + 1], e2 = edges[i + 2], e3 = edges[i + 3];
        float4 v0 = fetch(e0 & 0xFFFF);
        float4 v1 = fetch(e1 & 0xFFFF);
        float4 v2 = fetch(e2 & 0xFFFF);
        float4 v3 = fetch(e3 & 0xFFFF);
        accum(e0, v0); accum(e1, v1); accum(e2, v2); accum(e3, v3);
    }
    for (; i < end; ++i) {
        int ev = edges[i];
        accum(ev, fetch(ev & 0xFFFF));
    }

    float nrm = nodenorm[gw];
    a0.x *= nrm; a0.y *= nrm; a0.z *= nrm; a0.w *= nrm;
    a1.x *= nrm; a1.y *= nrm; a1.z *= nrm; a1.w *= nrm;
    a2.x *= nrm; a2.y *= nrm; a2.z *= nrm; a2.w *= nrm;
    a3.x *= nrm; a3.y *= nrm; a3.z *= nrm; a3.w *= nrm;

    uint2 ph, pl;
    size_t base = (size_t)gw * 512 + lane * 4;
    split4h(a0, ph, pl);
    *(uint2*)(Phi + base) = ph;           *(uint2*)(Plo + base) = pl;
    split4h(a1, ph, pl);
    *(uint2*)(Phi + base + 128) = ph;     *(uint2*)(Plo + base + 128) = pl;
    split4h(a2, ph, pl);
    *(uint2*)(Phi + base + 256) = ph;     *(uint2*)(Plo + base + 256) = pl;
    split4h(a3, ph, pl);
    *(uint2*)(Phi + base + 384) = ph;     *(uint2*)(Plo + base + 384) = pl;
}

// ================= launcher =================
extern "C" void kernel_launch(void* const* d_in, const int* in_sizes, int n_in,
                              void* d_out, int out_size) {
    const float* node_feat = (const float*)d_in[0];
    const float* W_emb     = (const float*)d_in[1];
    const float* b_emb     = (const float*)d_in[2];
    const float* bases     = (const float*)d_in[3];
    const float* w_coe     = (const float*)d_in[4];
    const float* self_loop = (const float*)d_in[5];
    const float* bn_gamma  = (const float*)d_in[6];
    const float* bn_beta   = (const float*)d_in[7];
    const float* bn_mean   = (const float*)d_in[8];
    const float* bn_var    = (const float*)d_in[9];
    const int*   src       = (const int*)d_in[10];
    const int*   dst       = (const int*)d_in[11];
    const int*   etype     = (const int*)d_in[12];

    float* nodenorm;
    __half *hA_hi, *hA_lo, *hB_hi, *hB_lo, *nf_hi, *nf_lo;
    __half *P_hi, *P_lo, *Bc_h, *We_h;
    int *cnt, *deg, *rowptr, *cursor, *bsum, *edges;
    cudaGetSymbolAddress((void**)&hA_hi, g_hA_hi);
    cudaGetSymbolAddress((void**)&hA_lo, g_hA_lo);
    cudaGetSymbolAddress((void**)&hB_hi, g_hB_hi);
    cudaGetSymbolAddress((void**)&hB_lo, g_hB_lo);
    cudaGetSymbolAddress((void**)&nf_hi, g_nf_hi);
    cudaGetSymbolAddress((void**)&nf_lo, g_nf_lo);
    cudaGetSymbolAddress((void**)&P_hi, g_P_hi);
    cudaGetSymbolAddress((void**)&P_lo, g_P_lo);
    cudaGetSymbolAddress((void**)&Bc_h, g_Bc_h);
    cudaGetSymbolAddress((void**)&We_h, g_We_h);
    cudaGetSymbolAddress((void**)&cnt, g_cnt);
    cudaGetSymbolAddress((void**)&nodenorm, g_nodenorm);
    cudaGetSymbolAddress((void**)&deg, g_deg);
    cudaGetSymbolAddress((void**)&rowptr, g_rowptr);
    cudaGetSymbolAddress((void**)&cursor, g_cursor);
    cudaGetSymbolAddress((void**)&bsum, g_bsum);
    cudaGetSymbolAddress((void**)&edges, g_edges);

    cudaFuncSetAttribute(mma_gemm, cudaFuncAttributeMaxDynamicSharedMemorySize, SMEM_GEMM_TOTAL);

    const int NB = (NN + 255) / 256;   // 196
    dim3 ggrid(1, (NN + 63) / 64);     // 782 tiles

    // [0] zero counts
    cudaMemsetAsync(cnt, 0, (size_t)RR * NN * sizeof(int));
    // [1] fused prep
    prep_kernel<<<PB_BC1, 256>>>(node_feat, W_emb, bases, self_loop, dst, etype, cnt,
                                 nf_hi, nf_lo, We_h,
                                 &Bc_h[0], &Bc_h[(size_t)DD * KCAT]);
    // [2] embedding GEMM: hA(hi/lo) = nf @ W_emb + b_emb   (no fp32 out)
    {
        GemmChunks ce = {};
        ce.n = 2;
        for (int c = 0; c < 2; ++c) {
            ce.c[c].Ahi = nf_hi + c * KCH; ce.c[c].Alo = nf_lo + c * KCH; ce.c[c].lda = DD;
            ce.c[c].Bh  = We_h + c * KCH;  ce.c[c].ldb = DD;
        }
        mma_gemm<<<ggrid, 256, SMEM_GEMM_TOTAL>>>(ce, b_emb, nullptr, nullptr, nullptr, nullptr,
                                                  nullptr, hA_hi, hA_lo, NN);
    }
    // [3-5] CSR chain
    normd_kernel<<<NB, 256>>>(cnt, nodenorm, deg, bsum);
    scan3<<<NB, 256>>>(deg, bsum, rowptr, cursor);
    fill_kernel<<<(EE + 255) / 256, 256>>>(src, dst, etype, cursor, edges);

    for (int l = 0; l < LL; ++l) {
        __half* hin_hi = l ? hB_hi : hA_hi;
        __half* hin_lo = l ? hB_lo : hA_lo;
        __half* hout_hi = l ? nullptr : hB_hi;   // last layer: skip split
        __half* hout_lo = l ? nullptr : hB_lo;
        float*  hout_f  = l ? (float*)d_out : nullptr;   // last layer: write d_out directly
        __half* bch = Bc_h + (size_t)l * DD * KCAT;

        gather_kernel<<<(NN * 32 + 255) / 256, 256>>>(rowptr, edges, hin_hi, hin_lo, nodenorm,
                                                      w_coe, l, P_hi, P_lo);
        GemmChunks cl = {};
        cl.n = 10;
        for (int c = 0; c < 10; ++c) {
            if (c < 8) {
                cl.c[c].Ahi = P_hi + c * KCH; cl.c[c].Alo = P_lo + c * KCH; cl.c[c].lda = 512;
            } else {
                cl.c[c].Ahi = hin_hi + (c - 8) * KCH;
                cl.c[c].Alo = hin_lo + (c - 8) * KCH;
                cl.c[c].lda = DD;
            }
            cl.c[c].Bh  = bch + c * KCH;
            cl.c[c].ldb = KCAT;
        }
        mma_gemm<<<ggrid, 256, SMEM_GEMM_TOTAL>>>(cl, nullptr,
                                                  bn_gamma + (size_t)l * DD,
                                                  bn_beta  + (size_t)l * DD,
                                                  bn_mean  + (size_t)l * DD,
                                                  bn_var   + (size_t)l * DD,
                                                  hout_f, hout_hi, hout_lo, NN);
    }
}